// round 10
// baseline (speedup 1.0000x reference)
#include <cuda_runtime.h>
#include <cuda_bf16.h>
#include <math.h>

typedef unsigned long long ull;

// ---------------- packed f32x2 helpers (scalar kernels) ----------------
__device__ __forceinline__ ull pack2(float lo, float hi) {
    ull r; asm("mov.b64 %0, {%1, %2};" : "=l"(r) : "f"(lo), "f"(hi)); return r;
}
__device__ __forceinline__ ull bc2(float v) { return pack2(v, v); }
__device__ __forceinline__ void ffma2(ull& d, ull a, ull b) {
    asm("fma.rn.f32x2 %0, %1, %2, %0;" : "+l"(d) : "l"(a), "l"(b));
}
__device__ __forceinline__ float lo32(ull v) { return __uint_as_float((unsigned)v); }
__device__ __forceinline__ float hi32(ull v) { return __uint_as_float((unsigned)(v >> 32)); }

// ---------------- mma.sync helpers ----------------
__device__ __forceinline__ unsigned s2u(const void* p) {
    unsigned a; asm("{ .reg .u64 t; cvta.to.shared.u64 t, %1; cvt.u32.u64 %0, t; }" : "=r"(a) : "l"(p));
    return a;
}
__device__ __forceinline__ void ldsm4t(unsigned* r, unsigned addr) {
    asm volatile("ldmatrix.sync.aligned.m8n8.x4.trans.shared.b16 {%0,%1,%2,%3}, [%4];"
                 : "=r"(r[0]), "=r"(r[1]), "=r"(r[2]), "=r"(r[3]) : "r"(addr));
}
__device__ __forceinline__ void mma16816(float* c, const unsigned* a, const unsigned* b) {
    asm volatile(
        "mma.sync.aligned.m16n8k16.row.col.f32.bf16.bf16.f32 "
        "{%0,%1,%2,%3}, {%4,%5,%6,%7}, {%8,%9}, {%0,%1,%2,%3};"
        : "+f"(c[0]), "+f"(c[1]), "+f"(c[2]), "+f"(c[3])
        : "r"(a[0]), "r"(a[1]), "r"(a[2]), "r"(a[3]), "r"(b[0]), "r"(b[1]));
}

// ---------------- scratch ----------------
#define BATCH 32
__device__ float g_A[BATCH*64*64*64];
__device__ float g_B[BATCH*128*32*32];
__device__ float g_C[BATCH*128*32*32];
__device__ float g_R[BATCH*32*32*32];
__device__ float g_Z[BATCH*64*32*32];
__device__ float g_Q[BATCH*64*32*32];
__device__ int   g_hist[512];
__device__ float g_ssep[256];
// shifted-plane staging for 3x3 convs
__device__ __align__(16) __nv_bfloat16 g_Sh[3*4096*1088];
__device__ __align__(16) __nv_bfloat16 g_Sl[3*4096*1088];
// generic im2col staging (max: conv2 K=1024 x Mtot=32768)
__device__ __align__(16) __nv_bfloat16 g_Gh[1024*32768];
__device__ __align__(16) __nv_bfloat16 g_Gl[1024*32768];
// staged weights (3x3: [tap][ci][oc]; generic: [k][oc]) — 9*128*128 covers both
__device__ __align__(16) __nv_bfloat16 g_Wh[9*128*128];
__device__ __align__(16) __nv_bfloat16 g_Wl[9*128*128];

__global__ void zero_kernel(int* hist) {
    int t = blockIdx.x * blockDim.x + threadIdx.x;
    if (t < 512) hist[t] = 0;
}

// ---------------- stage input (3x3 shifted planes) ----------------
__global__ void stage_in_kernel(const float* __restrict__ in, __nv_bfloat16* __restrict__ sh,
                                __nv_bfloat16* __restrict__ sl, int NP, int doRelu)
{
    int plane = blockIdx.x;
    const float* src = in + (size_t)plane * 1024;
    for (int i = threadIdx.x; i < 3*1088; i += 256) {
        int kx = i / 1088; int r = (i % 1088) / 32; int c = i & 31;
        float v = 0.f;
        int sy = r - 1, sx = c + kx - 1;
        if ((unsigned)sy < 32u && (unsigned)sx < 32u) v = src[sy*32 + sx];
        if (doRelu) v = fmaxf(v, 0.f);
        __nv_bfloat16 h = __float2bfloat16(v);
        __nv_bfloat16 l = __float2bfloat16(v - __bfloat162float(h));
        size_t o = ((size_t)kx * NP + plane) * 1088 + r*32 + c;
        sh[o] = h; sl[o] = l;
    }
}

// ---------------- stage weights (3x3: [tap][ci][oc]) ----------------
__global__ void stage_w_kernel(const float* __restrict__ w, __nv_bfloat16* __restrict__ wh,
                               __nv_bfloat16* __restrict__ wl, int Cin, int Cout)
{
    int n = Cin * Cout * 9;
    for (int i = blockIdx.x*256 + threadIdx.x; i < n; i += gridDim.x*256) {
        int oc = i / (Cin*9); int rr = i % (Cin*9); int ci = rr / 9; int t = rr % 9;
        float v = w[i];
        __nv_bfloat16 h = __float2bfloat16(v);
        __nv_bfloat16 l = __float2bfloat16(v - __bfloat162float(h));
        size_t dst = ((size_t)t * Cin + ci) * Cout + oc;
        wh[dst] = h; wl[dst] = l;
    }
}

// ---------------- generic im2col stage: A[k][m], k=t*CinP+ci, m=b*Mimg+pos ----------------
__global__ void stage_im2col(const float* __restrict__ in, __nv_bfloat16* __restrict__ ah,
                             __nv_bfloat16* __restrict__ al,
                             int Cin, int CinP, int Hin, int Win, int KW,
                             int stride, int pad, int Hout, int Wout, int Mtot)
{
    int k = blockIdx.x;
    int t = k / CinP, ci = k % CinP;
    int ky = t / KW, kx = t % KW;
    int Mimg = Hout * Wout;
    __nv_bfloat16* dh = ah + (size_t)k * Mtot;
    __nv_bfloat16* dl = al + (size_t)k * Mtot;
    int seg = Mtot / gridDim.y;
    int mend = seg * (blockIdx.y + 1);
    for (int m = seg * blockIdx.y + threadIdx.x; m < mend; m += 256) {
        int b = m / Mimg, pos = m % Mimg;
        int y = pos / Wout, x = pos % Wout;
        float v = 0.f;
        if (ci < Cin) {
            int iy = y*stride - pad + ky, ix = x*stride - pad + kx;
            if ((unsigned)iy < (unsigned)Hin && (unsigned)ix < (unsigned)Win)
                v = in[((size_t)(b*Cin + ci)*Hin + iy)*Win + ix];
        }
        __nv_bfloat16 h = __float2bfloat16(v);
        __nv_bfloat16 l = __float2bfloat16(v - __bfloat162float(h));
        dh[m] = h; dl[m] = l;
    }
}

// ---------------- generic weight stage: W[k][oc], OIHW source ----------------
__global__ void stage_w_gen(const float* __restrict__ w, __nv_bfloat16* __restrict__ wh,
                            __nv_bfloat16* __restrict__ wl,
                            int Cin, int CinP, int Cout, int T)
{
    int K = T * CinP;
    int ntot = K * Cout;
    for (int i = blockIdx.x*256 + threadIdx.x; i < ntot; i += gridDim.x*256) {
        int k = i / Cout, oc = i % Cout;
        int t = k / CinP, ci = k % CinP;
        float v = (ci < Cin) ? w[((size_t)oc*Cin + ci)*T + t] : 0.f;
        __nv_bfloat16 h = __float2bfloat16(v);
        __nv_bfloat16 l = __float2bfloat16(v - __bfloat162float(h));
        wh[(size_t)k*Cout + oc] = h; wl[(size_t)k*Cout + oc] = l;
    }
}

// ---------------- generic GEMM (warp-MMA, split-bf16 3-pass) ----------------
// A: [K][Mtot] staged; W: [K][Cout] staged. grid(Mtot/128, Cout/NT). 256 thr.
__global__ void __launch_bounds__(256)
gemm_wmma(const __nv_bfloat16* __restrict__ ah, const __nv_bfloat16* __restrict__ al,
          const __nv_bfloat16* __restrict__ wh, const __nv_bfloat16* __restrict__ wl,
          const float* __restrict__ bias, float* __restrict__ out,
          int K, int Cout, int NT, int Mtot, int Mimg, int outRelu)
{
    __shared__ __align__(16) __nv_bfloat16 sAh[32*136], sAl[32*136];
    __shared__ __align__(16) __nv_bfloat16 sBh[32*72],  sBl[32*72];
    int tid = threadIdx.x, lane = tid & 31, warp = tid >> 5;
    int wm = warp >> 1, wn = warp & 1;
    int warpN = NT >> 1, nfrags = warpN >> 3;
    unsigned aH = s2u(sAh), aL = s2u(sAl), bH = s2u(sBh), bL = s2u(sBl);

    int m0 = blockIdx.x * 128, ocb = blockIdx.y * NT;
    float acc[2][4][4];
#pragma unroll
    for (int mf = 0; mf < 2; mf++)
#pragma unroll
        for (int nf = 0; nf < 4; nf++)
#pragma unroll
            for (int j = 0; j < 4; j++) acc[mf][nf][j] = 0.f;

    int sub = lane >> 3, r = lane & 7;
    int nb = NT >> 3;

    for (int kc = 0; kc < K; kc += 32) {
        for (int i = tid; i < 512; i += 256) {
            int kk = i >> 4, q = i & 15;
            size_t go = (size_t)(kc + kk) * Mtot + m0;
            ((uint4*)(sAh + kk*136))[q] = ((const uint4*)(ah + go))[q];
            ((uint4*)(sAl + kk*136))[q] = ((const uint4*)(al + go))[q];
        }
        for (int i = tid; i < 32*nb; i += 256) {
            int kk = i / nb, q = i % nb;
            size_t wsrc = (size_t)(kc + kk) * Cout + ocb;
            ((uint4*)(sBh + kk*72))[q] = ((const uint4*)(wh + wsrc))[q];
            ((uint4*)(sBl + kk*72))[q] = ((const uint4*)(wl + wsrc))[q];
        }
        __syncthreads();
#pragma unroll
        for (int kf = 0; kf < 2; kf++) {
            unsigned Ah[2][4], Al[2][4];
            int akrow = kf*16 + ((sub & 2) ? 8 : 0) + r;
            int acoff = (sub & 1) ? 8 : 0;
#pragma unroll
            for (int mf = 0; mf < 2; mf++) {
                unsigned off = (unsigned)(akrow*136 + wm*32 + mf*16 + acoff) * 2;
                ldsm4t(Ah[mf], aH + off);
                ldsm4t(Al[mf], aL + off);
            }
            unsigned Bh[4][2], Bl[4][2];
            int bkrow = kf*16 + ((sub & 1) ? 8 : 0) + r;
            int bcoff = (sub & 2) ? 8 : 0;
#pragma unroll
            for (int nf2 = 0; nf2 < 4; nf2 += 2) {
                if (nf2 < nfrags) {
                    unsigned off = (unsigned)(bkrow*72 + wn*warpN + nf2*8 + bcoff) * 2;
                    unsigned t4[4];
                    ldsm4t(t4, bH + off);
                    Bh[nf2][0] = t4[0]; Bh[nf2][1] = t4[1];
                    Bh[nf2+1][0] = t4[2]; Bh[nf2+1][1] = t4[3];
                    ldsm4t(t4, bL + off);
                    Bl[nf2][0] = t4[0]; Bl[nf2][1] = t4[1];
                    Bl[nf2+1][0] = t4[2]; Bl[nf2+1][1] = t4[3];
                }
            }
#pragma unroll
            for (int mf = 0; mf < 2; mf++)
#pragma unroll
                for (int nf = 0; nf < 4; nf++) {
                    if (nf < nfrags) {
                        mma16816(acc[mf][nf], Ah[mf], Bh[nf]);
                        mma16816(acc[mf][nf], Ah[mf], Bl[nf]);
                        mma16816(acc[mf][nf], Al[mf], Bh[nf]);
                    }
                }
        }
        __syncthreads();
    }

    int g = lane >> 2, tig = lane & 3;
    int b = m0 / Mimg;
    int base = m0 - b * Mimg;
    float* ob = out + (size_t)b * Cout * Mimg;
#pragma unroll
    for (int mf = 0; mf < 2; mf++) {
        int p1 = base + wm*32 + mf*16 + g;
        int p2 = p1 + 8;
#pragma unroll
        for (int nf = 0; nf < 4; nf++) {
            if (nf < nfrags) {
                int n0 = ocb + wn*warpN + nf*8 + 2*tig;
                float b0 = bias ? bias[n0] : 0.f;
                float b1 = bias ? bias[n0+1] : 0.f;
                float v00 = acc[mf][nf][0] + b0, v01 = acc[mf][nf][1] + b1;
                float v10 = acc[mf][nf][2] + b0, v11 = acc[mf][nf][3] + b1;
                if (outRelu) {
                    v00 = fmaxf(v00, 0.f); v01 = fmaxf(v01, 0.f);
                    v10 = fmaxf(v10, 0.f); v11 = fmaxf(v11, 0.f);
                }
                ob[(size_t)n0*Mimg + p1]     = v00;
                ob[(size_t)(n0+1)*Mimg + p1] = v01;
                ob[(size_t)n0*Mimg + p2]     = v10;
                ob[(size_t)(n0+1)*Mimg + p2] = v11;
            }
        }
    }
}

// ---------------- warp-MMA 3x3 conv (proven R9) ----------------
__global__ void __launch_bounds__(256)
conv3x3_wmma(const __nv_bfloat16* __restrict__ sh, const __nv_bfloat16* __restrict__ sl,
             const __nv_bfloat16* __restrict__ wh, const __nv_bfloat16* __restrict__ wl,
             const float* __restrict__ bias, float* __restrict__ out,
             int Cin, int Cout, int NT, int NP)
{
    __shared__ __align__(16) __nv_bfloat16 sAh[32*136], sAl[32*136];
    __shared__ __align__(16) __nv_bfloat16 sBh[32*72],  sBl[32*72];
    int tid = threadIdx.x, lane = tid & 31, warp = tid >> 5;
    int wm = warp >> 1, wn = warp & 1;
    int warpN = NT >> 1;
    int nfrags = warpN >> 3;
    unsigned aH = s2u(sAh), aL = s2u(sAl), bH = s2u(sBh), bL = s2u(sBl);

    int y0 = blockIdx.x * 4, ocb = blockIdx.y * NT, b = blockIdx.z;
    float acc[2][4][4];
#pragma unroll
    for (int mf = 0; mf < 2; mf++)
#pragma unroll
        for (int nf = 0; nf < 4; nf++)
#pragma unroll
            for (int j = 0; j < 4; j++) acc[mf][nf][j] = 0.f;

    int sub = lane >> 3, r = lane & 7;
    int nb = NT >> 3;

    for (int tap = 0; tap < 9; tap++) {
        int ky = tap / 3, kx = tap % 3;
        for (int c0 = 0; c0 < Cin; c0 += 32) {
            size_t gbase = (size_t)kx * NP + (size_t)b * Cin + c0;
            for (int i = tid; i < 512; i += 256) {
                int ci = i >> 4, q = i & 15;
                size_t go = (gbase + ci) * 1088 + (size_t)(y0 + ky) * 32;
                ((uint4*)(sAh + ci*136))[q] = ((const uint4*)(sh + go))[q];
                ((uint4*)(sAl + ci*136))[q] = ((const uint4*)(sl + go))[q];
            }
            for (int i = tid; i < 32*nb; i += 256) {
                int ci = i / nb, q = i % nb;
                size_t wsrc = ((size_t)tap * Cin + c0 + ci) * Cout + ocb;
                ((uint4*)(sBh + ci*72))[q] = ((const uint4*)(wh + wsrc))[q];
                ((uint4*)(sBl + ci*72))[q] = ((const uint4*)(wl + wsrc))[q];
            }
            __syncthreads();
#pragma unroll
            for (int kf = 0; kf < 2; kf++) {
                unsigned Ah[2][4], Al[2][4];
                int akrow = kf*16 + ((sub & 2) ? 8 : 0) + r;
                int acoff = (sub & 1) ? 8 : 0;
#pragma unroll
                for (int mf = 0; mf < 2; mf++) {
                    unsigned off = (unsigned)(akrow*136 + wm*32 + mf*16 + acoff) * 2;
                    ldsm4t(Ah[mf], aH + off);
                    ldsm4t(Al[mf], aL + off);
                }
                unsigned Bh[4][2], Bl[4][2];
                int bkrow = kf*16 + ((sub & 1) ? 8 : 0) + r;
                int bcoff = (sub & 2) ? 8 : 0;
#pragma unroll
                for (int nf2 = 0; nf2 < 4; nf2 += 2) {
                    if (nf2 < nfrags) {
                        unsigned off = (unsigned)(bkrow*72 + wn*warpN + nf2*8 + bcoff) * 2;
                        unsigned t4[4];
                        ldsm4t(t4, bH + off);
                        Bh[nf2][0] = t4[0]; Bh[nf2][1] = t4[1];
                        Bh[nf2+1][0] = t4[2]; Bh[nf2+1][1] = t4[3];
                        ldsm4t(t4, bL + off);
                        Bl[nf2][0] = t4[0]; Bl[nf2][1] = t4[1];
                        Bl[nf2+1][0] = t4[2]; Bl[nf2+1][1] = t4[3];
                    }
                }
#pragma unroll
                for (int mf = 0; mf < 2; mf++)
#pragma unroll
                    for (int nf = 0; nf < 4; nf++) {
                        if (nf < nfrags) {
                            mma16816(acc[mf][nf], Ah[mf], Bh[nf]);
                            mma16816(acc[mf][nf], Ah[mf], Bl[nf]);
                            mma16816(acc[mf][nf], Al[mf], Bh[nf]);
                        }
                    }
            }
            __syncthreads();
        }
    }

    int g = lane >> 2, tig = lane & 3;
    float* ob = out + (size_t)b * Cout * 1024;
#pragma unroll
    for (int mf = 0; mf < 2; mf++) {
        int m1 = wm*32 + mf*16 + g;
        int m2 = m1 + 8;
        int p1 = (y0 + (m1 >> 5))*32 + (m1 & 31);
        int p2 = (y0 + (m2 >> 5))*32 + (m2 & 31);
#pragma unroll
        for (int nf = 0; nf < 4; nf++) {
            if (nf < nfrags) {
                int n0 = ocb + wn*warpN + nf*8 + 2*tig;
                float b0 = bias ? bias[n0] : 0.f;
                float b1 = bias ? bias[n0+1] : 0.f;
                ob[(size_t)n0*1024 + p1]     = acc[mf][nf][0] + b0;
                ob[(size_t)(n0+1)*1024 + p1] = acc[mf][nf][1] + b1;
                ob[(size_t)n0*1024 + p2]     = acc[mf][nf][2] + b0;
                ob[(size_t)(n0+1)*1024 + p2] = acc[mf][nf][3] + b1;
            }
        }
    }
}

// ---------------- conv 1x1: relu(in) @ w, +bias, +res ----------------
__global__ void __launch_bounds__(256, 3)
conv1x1_f2_kernel(const float* __restrict__ in, const float* __restrict__ w,
                  const float* __restrict__ bias, const float* __restrict__ hres,
                  float* __restrict__ out, int Cin, int Cout)
{
    __shared__ ull s_w[128][16];
    int tid = threadIdx.x;
    int pos = tid & 63, ocg = tid >> 6;
    int s0 = blockIdx.x * 256 + pos * 4;
    int ocb = blockIdx.y * 32;
    int b = blockIdx.z;
    float* swf = (float*)s_w;
    for (int i = tid; i < Cin * 32; i += 256) {
        int ocl = i / Cin; int ci = i % Cin;
        swf[ci*32 + ocl] = w[(ocb + ocl)*Cin + ci];
    }
    __syncthreads();
    ull acc[4][4];
#pragma unroll
    for (int p = 0; p < 4; p++)
#pragma unroll
        for (int j = 0; j < 4; j++) acc[p][j] = 0ull;

    for (int ci = 0; ci < Cin; ci++) {
        float4 iv = *(const float4*)&in[((size_t)(b*Cin + ci) << 10) + s0];
        ull b0 = bc2(fmaxf(iv.x, 0.f)), b1 = bc2(fmaxf(iv.y, 0.f));
        ull b2 = bc2(fmaxf(iv.z, 0.f)), b3 = bc2(fmaxf(iv.w, 0.f));
        ull wr[4];
#pragma unroll
        for (int j = 0; j < 4; j++) wr[j] = s_w[ci][ocg*4 + j];
#pragma unroll
        for (int j = 0; j < 4; j++) {
            ffma2(acc[0][j], b0, wr[j]);
            ffma2(acc[1][j], b1, wr[j]);
            ffma2(acc[2][j], b2, wr[j]);
            ffma2(acc[3][j], b3, wr[j]);
        }
    }
#pragma unroll
    for (int j = 0; j < 4; j++) {
#pragma unroll
        for (int lane = 0; lane < 2; lane++) {
            int oc = ocb + ocg*8 + 2*j + lane;
            size_t base = (((size_t)b*Cout + oc) << 10) + s0;
            float bv = bias ? bias[oc] : 0.f;
            float4 hv = make_float4(0.f, 0.f, 0.f, 0.f);
            if (hres) hv = *(const float4*)&hres[base];
            float4 ov;
            ov.x = (lane ? hi32(acc[0][j]) : lo32(acc[0][j])) + bv + hv.x;
            ov.y = (lane ? hi32(acc[1][j]) : lo32(acc[1][j])) + bv + hv.y;
            ov.z = (lane ? hi32(acc[2][j]) : lo32(acc[2][j])) + bv + hv.z;
            ov.w = (lane ? hi32(acc[3][j]) : lo32(acc[3][j])) + bv + hv.w;
            *(float4*)&out[base] = ov;
        }
    }
}

// ---------------- vector quantizer ----------------
__global__ void vq_kernel(const float* __restrict__ z, const float* __restrict__ cb,
                          float* __restrict__ qc, int* __restrict__ hist,
                          float* __restrict__ ssep)
{
    __shared__ ull s_cb[128][32];
    __shared__ float s_cn[128];
    __shared__ int s_hist[512];
    __shared__ float s_red[128];
    int tid = threadIdx.x;
    for (int i = tid; i < 512; i += 128) s_hist[i] = 0;

    int n = blockIdx.x * 128 + tid;
    int b = n >> 10, s = n & 1023;
    ull zp[32];
    float zv[64];
#pragma unroll
    for (int d = 0; d < 64; d++) zv[d] = z[(((size_t)b * 64 + d) << 10) + s];
#pragma unroll
    for (int j = 0; j < 32; j++) zp[j] = pack2(zv[2*j], zv[2*j+1]);

    const ull* cbu = (const ull*)cb;
    float best = 3.4e38f; int bi = 0;
    for (int k0 = 0; k0 < 512; k0 += 128) {
        __syncthreads();
        for (int i = tid; i < 128*32; i += 128)
            s_cb[i >> 5][i & 31] = cbu[((size_t)k0 << 5) + i];
        __syncthreads();
        {
            float cn = 0.f;
#pragma unroll
            for (int j = 0; j < 32; j++) {
                ull p = s_cb[tid][j];
                float a = lo32(p), bb = hi32(p);
                cn += a*a + bb*bb;
            }
            s_cn[tid] = cn;
        }
        __syncthreads();
        for (int k = 0; k < 128; k++) {
            ull dp = 0ull;
#pragma unroll
            for (int j = 0; j < 32; j++) ffma2(dp, zp[j], s_cb[k][j]);
            float dot = lo32(dp) + hi32(dp);
            float dd = s_cn[k] - 2.f * dot;
            if (dd < best) { best = dd; bi = k0 + k; }
        }
    }
    float sq = 0.f;
    const float* c = cb + ((size_t)bi << 6);
#pragma unroll
    for (int d = 0; d < 64; d++) {
        float cv = c[d];
        qc[(((size_t)b * 64 + d) << 10) + s] = cv;
        float df = cv - zv[d];
        sq += df * df;
    }
    atomicAdd(&s_hist[bi], 1);
    s_red[tid] = sq;
    __syncthreads();
    for (int st = 64; st > 0; st >>= 1) {
        if (tid < st) s_red[tid] += s_red[tid + st];
        __syncthreads();
    }
    if (tid == 0) ssep[blockIdx.x] = s_red[0];
    for (int i = tid; i < 512; i += 128)
        if (s_hist[i]) atomicAdd(&hist[i], s_hist[i]);
}

// ---------------- dt1: convT k=4 s=2 p=1 packed ----------------
__global__ void __launch_bounds__(256, 2)
convt_f2_kernel(const float* __restrict__ in, const float* __restrict__ w,
                const float* __restrict__ bias, float* __restrict__ out,
                int Cin, int Cout)
{
    __shared__ float s_in[8][10][21];
    __shared__ ull s_w[8][16][16];
    int tid = threadIdx.x;
    int pos = tid & 31, ocg = tid >> 5;
    int posx = pos & 3, posy = pos >> 2;
    int col0 = posx * 8, row0 = posy * 2;
    int tx = blockIdx.x & 1, ty = blockIdx.x >> 1;
    int cx0 = tx * 32, ry0 = ty * 16;
    int ocb = blockIdx.y * 32;
    int b = blockIdx.z;
    ull acc[2][8][2];
#pragma unroll
    for (int r = 0; r < 2; r++)
#pragma unroll
        for (int c = 0; c < 8; c++)
#pragma unroll
            for (int j = 0; j < 2; j++) acc[r][c][j] = 0ull;

    float* swf = (float*)s_w;
    for (int c0 = 0; c0 < Cin; c0 += 8) {
        for (int i = tid; i < 8*10*18; i += 256) {
            int ci = i / 180; int rr = (i / 18) % 10; int cc = i % 18;
            int gy = (ry0 >> 1) - 1 + rr, gx = (cx0 >> 1) - 1 + cc;
            float v = 0.f;
            if ((unsigned)gy < 32u && (unsigned)gx < 32u)
                v = fmaxf(in[((b*Cin + c0 + ci)*32 + gy)*32 + gx], 0.f);
            s_in[ci][rr][cc] = v;
        }
        for (int i = tid; i < 32*128; i += 256) {
            int ocl = i >> 7; int t = i & 127; int ci = t >> 4; int k = t & 15;
            swf[(ci*16 + k)*32 + ocl] = w[((size_t)(ocb + ocl)*Cin + c0 + ci)*16 + k];
        }
        __syncthreads();
#pragma unroll
        for (int ci = 0; ci < 8; ci++) {
            ull vb[3][6];
#pragma unroll
            for (int rr = 0; rr < 3; rr++)
#pragma unroll
                for (int cc = 0; cc < 6; cc++)
                    vb[rr][cc] = bc2(s_in[ci][posy + rr][posx*4 + cc]);
#pragma unroll
            for (int r = 0; r < 2; r++) {
#pragma unroll
                for (int kxp = 0; kxp < 2; kxp++) {
                    ull wr[4][2];
                    int t0 = r*4 + kxp, t2 = (r+2)*4 + kxp;
#pragma unroll
                    for (int j = 0; j < 2; j++) {
                        wr[0][j] = s_w[ci][t0][ocg*2 + j];
                        wr[1][j] = s_w[ci][t0+2][ocg*2 + j];
                        wr[2][j] = s_w[ci][t2][ocg*2 + j];
                        wr[3][j] = s_w[ci][t2+2][ocg*2 + j];
                    }
#pragma unroll
                    for (int cs = 0; cs < 4; cs++) {
                        int c = 2*cs + kxp;
                        int cq = cs + kxp;
#pragma unroll
                        for (int j = 0; j < 2; j++) {
                            ffma2(acc[r][c][j], vb[r][cq],     wr[0][j]);
                            ffma2(acc[r][c][j], vb[r][cq+1],   wr[1][j]);
                            ffma2(acc[r][c][j], vb[r+1][cq],   wr[2][j]);
                            ffma2(acc[r][c][j], vb[r+1][cq+1], wr[3][j]);
                        }
                    }
                }
            }
        }
        __syncthreads();
    }
#pragma unroll
    for (int r = 0; r < 2; r++)
#pragma unroll
        for (int c = 0; c < 8; c++)
#pragma unroll
            for (int j = 0; j < 2; j++) {
                int oc = ocb + ocg*4 + 2*j;
                int oy = ry0 + row0 + r, ox = cx0 + col0 + c;
                float v0 = fmaxf(lo32(acc[r][c][j]) + bias[oc], 0.f);
                float v1 = fmaxf(hi32(acc[r][c][j]) + bias[oc+1], 0.f);
                out[(((size_t)b*Cout + oc)*64 + oy)*64 + ox] = v0;
                out[(((size_t)b*Cout + oc+1)*64 + oy)*64 + ox] = v1;
            }
}

// ---------------- dt2: convT (64->3), 4-oc ----------------
__global__ void convt4s2_kernel(const float* __restrict__ in, const float* __restrict__ w,
                                const float* __restrict__ bias, float* __restrict__ out,
                                int Cin, int Hin, int Win, int Cout, int inRelu, int outRelu)
{
    __shared__ float s_in[8][10][12];
    __shared__ float s_w[4][8][16];
    int tid = threadIdx.x;
    int Hout = Hin * 2, Wout = Win * 2;
    int ntx = Wout >> 4;
    int ox0 = (blockIdx.x % ntx) << 4, oy0 = (blockIdx.x / ntx) << 4;
    int b = blockIdx.z;
    int px = tid & 15, py = tid >> 4;
    int iy0 = oy0 >> 1, ix0 = ox0 >> 1;
    float acc[4];
#pragma unroll
    for (int i = 0; i < 4; i++) acc[i] = 0.f;

    for (int c0 = 0; c0 < Cin; c0 += 8) {
        for (int i = tid; i < 8 * 10 * 10; i += 256) {
            int ci = i / 100; int rr = (i / 10) % 10; int col = i % 10;
            int gy = iy0 - 1 + rr, gx = ix0 - 1 + col;
            float v = 0.f;
            if ((unsigned)gy < (unsigned)Hin && (unsigned)gx < (unsigned)Win)
                v = in[((b*Cin + c0 + ci)*Hin + gy)*Win + gx];
            if (inRelu) v = fmaxf(v, 0.f);
            s_in[ci][rr][col] = v;
        }
        for (int i = tid; i < 4 * 8 * 16; i += 256) {
            int oc = i >> 7; int ci = (i >> 4) & 7; int k = i & 15;
            s_w[oc][ci][k] = (oc < Cout) ? w[((size_t)oc * Cin + c0 + ci)*16 + k] : 0.f;
        }
        __syncthreads();
        int ky0 = py & 1, kx0 = px & 1;
        int r0 = (py + ky0) >> 1;
        int q0 = (px + kx0) >> 1;
#pragma unroll
        for (int ci = 0; ci < 8; ci++) {
            float v00 = s_in[ci][r0][q0];
            float v01 = s_in[ci][r0][q0 + 1];
            float v10 = s_in[ci][r0 + 1][q0];
            float v11 = s_in[ci][r0 + 1][q0 + 1];
#pragma unroll
            for (int oc = 0; oc < 4; oc++) {
                float a = acc[oc];
                a += v00 * s_w[oc][ci][ky0*4 + kx0];
                a += v01 * s_w[oc][ci][ky0*4 + kx0 + 2];
                a += v10 * s_w[oc][ci][(ky0+2)*4 + kx0];
                a += v11 * s_w[oc][ci][(ky0+2)*4 + kx0 + 2];
                acc[oc] = a;
            }
        }
        __syncthreads();
    }
#pragma unroll
    for (int oc = 0; oc < 4; oc++) {
        if (oc < Cout) {
            float r = acc[oc] + bias[oc];
            if (outRelu) r = fmaxf(r, 0.f);
            out[(((size_t)b * Cout + oc)*Hout + oy0 + py)*Wout + ox0 + px] = r;
        }
    }
}

// ---------------- finalize ----------------
__global__ void finalize_kernel(const int* __restrict__ hist, const float* __restrict__ ssep,
                                float* __restrict__ out, int lastIdx)
{
    __shared__ float red[512];
    __shared__ float red2[256];
    int t = threadIdx.x;
    float p = hist[t] * (1.0f / 32768.0f);
    red[t] = p * logf(p + 1e-10f);
    if (t < 256) red2[t] = ssep[t];
    __syncthreads();
    for (int st = 256; st > 0; st >>= 1) {
        if (t < st) red[t] += red[t + st];
        __syncthreads();
    }
    for (int st = 128; st > 0; st >>= 1) {
        if (t < st) red2[t] += red2[t + st];
        __syncthreads();
    }
    if (t == 0) {
        out[0] = red2[0] * 1.25f / (32768.0f * 64.0f);
        out[lastIdx] = expf(-red[0]);
    }
}

// ---------------- launch ----------------
extern "C" void kernel_launch(void* const* d_in, const int* in_sizes, int n_in,
                              void* d_out, int out_size)
{
    const float* x     = (const float*)d_in[0];
    const float* e_w1  = (const float*)d_in[1];
    const float* e_b1  = (const float*)d_in[2];
    const float* e_w2  = (const float*)d_in[3];
    const float* e_b2  = (const float*)d_in[4];
    const float* e_w3  = (const float*)d_in[5];
    const float* e_b3  = (const float*)d_in[6];
    const float* e_r1a = (const float*)d_in[7];
    const float* e_r1b = (const float*)d_in[8];
    const float* e_r2a = (const float*)d_in[9];
    const float* e_r2b = (const float*)d_in[10];
    const float* pre_w = (const float*)d_in[11];
    const float* pre_b = (const float*)d_in[12];
    const float* cb    = (const float*)d_in[13];
    const float* d_w1  = (const float*)d_in[14];
    const float* d_b1  = (const float*)d_in[15];
    const float* d_r1a = (const float*)d_in[16];
    const float* d_r1b = (const float*)d_in[17];
    const float* d_r2a = (const float*)d_in[18];
    const float* d_r2b = (const float*)d_in[19];
    const float* dt_w1 = (const float*)d_in[20];
    const float* dt_b1 = (const float*)d_in[21];
    const float* dt_w2 = (const float*)d_in[22];
    const float* dt_b2 = (const float*)d_in[23];
    float* out = (float*)d_out;

    float *A, *Bb, *C, *R, *Z, *Q, *ssep; int* hist;
    __nv_bfloat16 *Sh, *Sl, *Gh, *Gl, *Wh, *Wl;
    cudaGetSymbolAddress((void**)&A,    g_A);
    cudaGetSymbolAddress((void**)&Bb,   g_B);
    cudaGetSymbolAddress((void**)&C,    g_C);
    cudaGetSymbolAddress((void**)&R,    g_R);
    cudaGetSymbolAddress((void**)&Z,    g_Z);
    cudaGetSymbolAddress((void**)&Q,    g_Q);
    cudaGetSymbolAddress((void**)&ssep, g_ssep);
    cudaGetSymbolAddress((void**)&hist, g_hist);
    cudaGetSymbolAddress((void**)&Sh,   g_Sh);
    cudaGetSymbolAddress((void**)&Sl,   g_Sl);
    cudaGetSymbolAddress((void**)&Gh,   g_Gh);
    cudaGetSymbolAddress((void**)&Gl,   g_Gl);
    cudaGetSymbolAddress((void**)&Wh,   g_Wh);
    cudaGetSymbolAddress((void**)&Wl,   g_Wl);

    zero_kernel<<<2, 256>>>(hist);

    // ---- encoder ----
    // conv1: 3->64, k4s2, out 64x64, relu — im2col GEMM (K=16*4=64, M=32*4096)
    stage_w_gen<<<16, 256>>>(e_w1, Wh, Wl, 3, 4, 64, 16);
    stage_im2col<<<dim3(64, 8), 256>>>(x, Gh, Gl, 3, 4, 128, 128, 4, 2, 1, 64, 64, BATCH*4096);
    gemm_wmma<<<dim3(1024, 1), 256>>>(Gh, Gl, Wh, Wl, e_b1, A, 64, 64, 64, BATCH*4096, 4096, 1);
    // conv2: 64->128, k4s2, out 32x32, relu — im2col GEMM (K=16*64=1024, M=32*1024)
    stage_w_gen<<<128, 256>>>(e_w2, Wh, Wl, 64, 64, 128, 16);
    stage_im2col<<<dim3(1024, 2), 256>>>(A, Gh, Gl, 64, 64, 64, 64, 4, 2, 1, 32, 32, BATCH*1024);
    gemm_wmma<<<dim3(256, 2), 256>>>(Gh, Gl, Wh, Wl, e_b2, Bb, 1024, 128, 64, BATCH*1024, 1024, 1);

    // e3: 128->128 via shifted-plane wmma
    stage_w_kernel<<<64, 256>>>(e_w3, Wh, Wl, 128, 128);
    stage_in_kernel<<<4096, 256>>>(Bb, Sh, Sl, 4096, 0);
    conv3x3_wmma<<<dim3(8, 2, BATCH), 256>>>(Sh, Sl, Wh, Wl, e_b3, C, 128, 128, 64, 4096);
    // res1
    stage_w_kernel<<<64, 256>>>(e_r1a, Wh, Wl, 128, 32);
    stage_in_kernel<<<4096, 256>>>(C, Sh, Sl, 4096, 1);
    conv3x3_wmma<<<dim3(8, 1, BATCH), 256>>>(Sh, Sl, Wh, Wl, nullptr, R, 128, 32, 32, 4096);
    conv1x1_f2_kernel<<<dim3(4, 4, BATCH), 256>>>(R, e_r1b, nullptr, C, C, 32, 128);
    // res2
    stage_w_kernel<<<64, 256>>>(e_r2a, Wh, Wl, 128, 32);
    stage_in_kernel<<<4096, 256>>>(C, Sh, Sl, 4096, 1);
    conv3x3_wmma<<<dim3(8, 1, BATCH), 256>>>(Sh, Sl, Wh, Wl, nullptr, R, 128, 32, 32, 4096);
    conv1x1_f2_kernel<<<dim3(4, 4, BATCH), 256>>>(R, e_r2b, nullptr, C, C, 32, 128);
    // pre-VQ 1x1
    conv1x1_f2_kernel<<<dim3(4, 2, BATCH), 256>>>(C, pre_w, pre_b, nullptr, Z, 128, 64);

    // ---- VQ ----
    vq_kernel<<<256, 128>>>(Z, cb, Q, hist, ssep);

    // ---- decoder ----
    stage_w_kernel<<<64, 256>>>(d_w1, Wh, Wl, 64, 128);
    stage_in_kernel<<<2048, 256>>>(Q, Sh, Sl, 2048, 0);
    conv3x3_wmma<<<dim3(8, 2, BATCH), 256>>>(Sh, Sl, Wh, Wl, d_b1, Bb, 64, 128, 64, 2048);
    stage_w_kernel<<<64, 256>>>(d_r1a, Wh, Wl, 128, 32);
    stage_in_kernel<<<4096, 256>>>(Bb, Sh, Sl, 4096, 1);
    conv3x3_wmma<<<dim3(8, 1, BATCH), 256>>>(Sh, Sl, Wh, Wl, nullptr, R, 128, 32, 32, 4096);
    conv1x1_f2_kernel<<<dim3(4, 4, BATCH), 256>>>(R, d_r1b, nullptr, Bb, Bb, 32, 128);
    stage_w_kernel<<<64, 256>>>(d_r2a, Wh, Wl, 128, 32);
    stage_in_kernel<<<4096, 256>>>(Bb, Sh, Sl, 4096, 1);
    conv3x3_wmma<<<dim3(8, 1, BATCH), 256>>>(Sh, Sl, Wh, Wl, nullptr, R, 128, 32, 32, 4096);
    conv1x1_f2_kernel<<<dim3(4, 4, BATCH), 256>>>(R, d_r2b, nullptr, Bb, Bb, 32, 128);
    convt_f2_kernel<<<dim3(8, 2, BATCH), 256>>>(Bb, dt_w1, dt_b1, A, 128, 64);
    convt4s2_kernel<<<dim3(64, 1, BATCH), 256>>>(A, dt_w2, dt_b2, out + 1, 64, 64, 64, 3, 0, 0);

    finalize_kernel<<<1, 512>>>(hist, ssep, out, out_size - 1);
}

// round 11
// speedup vs baseline: 1.1834x; 1.1834x over previous
#include <cuda_runtime.h>
#include <cuda_bf16.h>
#include <math.h>

typedef unsigned long long ull;

// ---------------- packed f32x2 helpers (scalar kernels) ----------------
__device__ __forceinline__ ull pack2(float lo, float hi) {
    ull r; asm("mov.b64 %0, {%1, %2};" : "=l"(r) : "f"(lo), "f"(hi)); return r;
}
__device__ __forceinline__ ull bc2(float v) { return pack2(v, v); }
__device__ __forceinline__ void ffma2(ull& d, ull a, ull b) {
    asm("fma.rn.f32x2 %0, %1, %2, %0;" : "+l"(d) : "l"(a), "l"(b));
}
__device__ __forceinline__ float lo32(ull v) { return __uint_as_float((unsigned)v); }
__device__ __forceinline__ float hi32(ull v) { return __uint_as_float((unsigned)(v >> 32)); }

// ---------------- mma.sync / cp.async helpers ----------------
__device__ __forceinline__ unsigned s2u(const void* p) {
    unsigned a; asm("{ .reg .u64 t; cvta.to.shared.u64 t, %1; cvt.u32.u64 %0, t; }" : "=r"(a) : "l"(p));
    return a;
}
__device__ __forceinline__ void ldsm4t(unsigned* r, unsigned addr) {
    asm volatile("ldmatrix.sync.aligned.m8n8.x4.trans.shared.b16 {%0,%1,%2,%3}, [%4];"
                 : "=r"(r[0]), "=r"(r[1]), "=r"(r[2]), "=r"(r[3]) : "r"(addr));
}
__device__ __forceinline__ void mma16816(float* c, const unsigned* a, const unsigned* b) {
    asm volatile(
        "mma.sync.aligned.m16n8k16.row.col.f32.bf16.bf16.f32 "
        "{%0,%1,%2,%3}, {%4,%5,%6,%7}, {%8,%9}, {%0,%1,%2,%3};"
        : "+f"(c[0]), "+f"(c[1]), "+f"(c[2]), "+f"(c[3])
        : "r"(a[0]), "r"(a[1]), "r"(a[2]), "r"(a[3]), "r"(b[0]), "r"(b[1]));
}
__device__ __forceinline__ void cpa16(unsigned saddr, const void* g) {
    asm volatile("cp.async.cg.shared.global [%0], [%1], 16;" :: "r"(saddr), "l"(g));
}
__device__ __forceinline__ void cpa_commit() { asm volatile("cp.async.commit_group;" ::: "memory"); }
__device__ __forceinline__ void cpa_wait0() { asm volatile("cp.async.wait_group 0;" ::: "memory"); }

// smem buffer layout (bytes): Ah[32x136] Al Bh[32x72] Bl, double-buffered
#define BUFB 26624
#define AL_OFF 8704
#define BH_OFF 17408
#define BL_OFF 22016
#define DYN_SMEM 53248

// ---------------- scratch ----------------
#define BATCH 32
__device__ float g_A[BATCH*64*64*64];
__device__ float g_B[BATCH*128*32*32];
__device__ float g_C[BATCH*128*32*32];
__device__ float g_R[BATCH*32*32*32];
__device__ float g_Z[BATCH*64*32*32];
__device__ float g_Q[BATCH*64*32*32];
__device__ int   g_hist[512];
__device__ float g_ssep[256];
__device__ __align__(16) __nv_bfloat16 g_Sh[3*4096*1088];
__device__ __align__(16) __nv_bfloat16 g_Sl[3*4096*1088];
__device__ __align__(16) __nv_bfloat16 g_Gh[1024*32768];
__device__ __align__(16) __nv_bfloat16 g_Gl[1024*32768];
__device__ __align__(16) __nv_bfloat16 g_Wh[9*128*128];
__device__ __align__(16) __nv_bfloat16 g_Wl[9*128*128];

__global__ void zero_kernel(int* hist) {
    int t = blockIdx.x * blockDim.x + threadIdx.x;
    if (t < 512) hist[t] = 0;
}

// ---------------- stage input (3x3 shifted planes) ----------------
__global__ void stage_in_kernel(const float* __restrict__ in, __nv_bfloat16* __restrict__ sh,
                                __nv_bfloat16* __restrict__ sl, int NP, int doRelu)
{
    int plane = blockIdx.x;
    const float* src = in + (size_t)plane * 1024;
    for (int i = threadIdx.x; i < 3*1088; i += 256) {
        int kx = i / 1088; int r = (i % 1088) / 32; int c = i & 31;
        float v = 0.f;
        int sy = r - 1, sx = c + kx - 1;
        if ((unsigned)sy < 32u && (unsigned)sx < 32u) v = src[sy*32 + sx];
        if (doRelu) v = fmaxf(v, 0.f);
        __nv_bfloat16 h = __float2bfloat16(v);
        __nv_bfloat16 l = __float2bfloat16(v - __bfloat162float(h));
        size_t o = ((size_t)kx * NP + plane) * 1088 + r*32 + c;
        sh[o] = h; sl[o] = l;
    }
}

// ---------------- stage weights (3x3: [tap][ci][oc]) ----------------
__global__ void stage_w_kernel(const float* __restrict__ w, __nv_bfloat16* __restrict__ wh,
                               __nv_bfloat16* __restrict__ wl, int Cin, int Cout)
{
    int n = Cin * Cout * 9;
    for (int i = blockIdx.x*256 + threadIdx.x; i < n; i += gridDim.x*256) {
        int oc = i / (Cin*9); int rr = i % (Cin*9); int ci = rr / 9; int t = rr % 9;
        float v = w[i];
        __nv_bfloat16 h = __float2bfloat16(v);
        __nv_bfloat16 l = __float2bfloat16(v - __bfloat162float(h));
        size_t dst = ((size_t)t * Cin + ci) * Cout + oc;
        wh[dst] = h; wl[dst] = l;
    }
}

// ---------------- generic im2col stage (conv1) ----------------
__global__ void stage_im2col(const float* __restrict__ in, __nv_bfloat16* __restrict__ ah,
                             __nv_bfloat16* __restrict__ al,
                             int Cin, int CinP, int Hin, int Win, int KW,
                             int stride, int pad, int Hout, int Wout, int Mtot)
{
    int k = blockIdx.x;
    int t = k / CinP, ci = k % CinP;
    int ky = t / KW, kx = t % KW;
    int Mimg = Hout * Wout;
    __nv_bfloat16* dh = ah + (size_t)k * Mtot;
    __nv_bfloat16* dl = al + (size_t)k * Mtot;
    int seg = Mtot / gridDim.y;
    int mend = seg * (blockIdx.y + 1);
    for (int m = seg * blockIdx.y + threadIdx.x; m < mend; m += 256) {
        int b = m / Mimg, pos = m % Mimg;
        int y = pos / Wout, x = pos % Wout;
        float v = 0.f;
        if (ci < Cin) {
            int iy = y*stride - pad + ky, ix = x*stride - pad + kx;
            if ((unsigned)iy < (unsigned)Hin && (unsigned)ix < (unsigned)Win)
                v = in[((size_t)(b*Cin + ci)*Hin + iy)*Win + ix];
        }
        __nv_bfloat16 h = __float2bfloat16(v);
        __nv_bfloat16 l = __float2bfloat16(v - __bfloat162float(h));
        dh[m] = h; dl[m] = l;
    }
}

// ---------------- read-once tiled im2col for conv2 (Cin=64, 64x64 -> 32x32, k4s2p1) ----------------
__global__ void stage_k4s2(const float* __restrict__ in, __nv_bfloat16* __restrict__ gh,
                           __nv_bfloat16* __restrict__ gl, int Mtot)
{
    __shared__ float tile[67][68];
    int bci = blockIdx.x;                    // b*64 + ci
    const float* src = in + (size_t)bci * 4096;
    for (int i = threadIdx.x; i < 67*67; i += 256) {
        int r = i / 67, c = i % 67;          // input coords (r-1, c-1)
        float v = 0.f;
        int iy = r - 1, ix = c - 1;
        if ((unsigned)iy < 64u && (unsigned)ix < 64u) v = src[iy*64 + ix];
        tile[r][c] = v;
    }
    __syncthreads();
    int b = bci >> 6, ci = bci & 63;
    for (int i = threadIdx.x; i < 16*1024; i += 256) {
        int t = i >> 10, pos = i & 1023;
        int y = pos >> 5, x = pos & 31;
        int ky = t >> 2, kx = t & 3;
        float v = tile[2*y + ky][2*x + kx];  // iy=2y-1+ky -> idx 2y+ky
        __nv_bfloat16 h = __float2bfloat16(v);
        __nv_bfloat16 l = __float2bfloat16(v - __bfloat162float(h));
        size_t dst = ((size_t)(t*64 + ci)) * Mtot + (size_t)b*1024 + pos;
        gh[dst] = h; gl[dst] = l;
    }
}

// ---------------- generic weight stage: W[k][oc], OIHW source ----------------
__global__ void stage_w_gen(const float* __restrict__ w, __nv_bfloat16* __restrict__ wh,
                            __nv_bfloat16* __restrict__ wl,
                            int Cin, int CinP, int Cout, int T)
{
    int K = T * CinP;
    int ntot = K * Cout;
    for (int i = blockIdx.x*256 + threadIdx.x; i < ntot; i += gridDim.x*256) {
        int k = i / Cout, oc = i % Cout;
        int t = k / CinP, ci = k % CinP;
        float v = (ci < Cin) ? w[((size_t)oc*Cin + ci)*T + t] : 0.f;
        __nv_bfloat16 h = __float2bfloat16(v);
        __nv_bfloat16 l = __float2bfloat16(v - __bfloat162float(h));
        wh[(size_t)k*Cout + oc] = h; wl[(size_t)k*Cout + oc] = l;
    }
}

// ---------------- generic GEMM, cp.async double-buffered ----------------
// A: [K][Mtot]; W: [K][Cout]. grid(Mtot/128, Cout/NT). 256 thr. NT=64.
__global__ void __launch_bounds__(256)
gemm_wmma(const __nv_bfloat16* __restrict__ ah, const __nv_bfloat16* __restrict__ al,
          const __nv_bfloat16* __restrict__ wh, const __nv_bfloat16* __restrict__ wl,
          const float* __restrict__ bias, float* __restrict__ out,
          int K, int Cout, int NT, int Mtot, int Mimg, int outRelu)
{
    extern __shared__ char dyn[];
    unsigned sm0 = s2u(dyn);
    int tid = threadIdx.x, lane = tid & 31, warp = tid >> 5;
    int wm = warp >> 1, wn = warp & 1;
    int warpN = NT >> 1, nfrags = warpN >> 3;
    int m0 = blockIdx.x * 128, ocb = blockIdx.y * NT;
    int nb = NT >> 3;
    int nch = K >> 5;
    float acc[2][4][4];
#pragma unroll
    for (int mf = 0; mf < 2; mf++)
#pragma unroll
        for (int nf = 0; nf < 4; nf++)
#pragma unroll
            for (int j = 0; j < 4; j++) acc[mf][nf][j] = 0.f;
    int sub = lane >> 3, r = lane & 7;

    auto LD = [&](int c, int bufi) {
        int kc = c << 5;
        unsigned base = sm0 + bufi * BUFB;
        for (int i = tid; i < 512; i += 256) {
            int kk = i >> 4, q = i & 15;
            size_t go = (size_t)(kc + kk) * Mtot + m0 + q*8;
            cpa16(base + kk*272 + q*16, ah + go);
            cpa16(base + AL_OFF + kk*272 + q*16, al + go);
        }
        for (int i = tid; i < 32*nb; i += 256) {
            int kk = i / nb, q = i % nb;
            size_t wsrc = (size_t)(kc + kk) * Cout + ocb + q*8;
            cpa16(base + BH_OFF + kk*144 + q*16, wh + wsrc);
            cpa16(base + BL_OFF + kk*144 + q*16, wl + wsrc);
        }
    };

    LD(0, 0); cpa_commit(); cpa_wait0(); __syncthreads();
    for (int c = 0; c < nch; c++) {
        int bi = c & 1;
        if (c + 1 < nch) { LD(c + 1, bi ^ 1); cpa_commit(); }
        unsigned aHb = sm0 + bi*BUFB, aLb = aHb + AL_OFF, bHb = aHb + BH_OFF, bLb = aHb + BL_OFF;
#pragma unroll
        for (int kf = 0; kf < 2; kf++) {
            unsigned Ah[2][4], Al[2][4];
            int akrow = kf*16 + ((sub & 2) ? 8 : 0) + r;
            int acoff = (sub & 1) ? 8 : 0;
#pragma unroll
            for (int mf = 0; mf < 2; mf++) {
                unsigned off = (unsigned)(akrow*272 + (wm*32 + mf*16 + acoff)*2);
                ldsm4t(Ah[mf], aHb + off);
                ldsm4t(Al[mf], aLb + off);
            }
            unsigned Bh[4][2], Bl[4][2];
            int bkrow = kf*16 + ((sub & 1) ? 8 : 0) + r;
            int bcoff = (sub & 2) ? 8 : 0;
#pragma unroll
            for (int nf2 = 0; nf2 < 4; nf2 += 2) {
                if (nf2 < nfrags) {
                    unsigned off = (unsigned)(bkrow*144 + (wn*warpN + nf2*8 + bcoff)*2);
                    unsigned t4[4];
                    ldsm4t(t4, bHb + off);
                    Bh[nf2][0] = t4[0]; Bh[nf2][1] = t4[1];
                    Bh[nf2+1][0] = t4[2]; Bh[nf2+1][1] = t4[3];
                    ldsm4t(t4, bLb + off);
                    Bl[nf2][0] = t4[0]; Bl[nf2][1] = t4[1];
                    Bl[nf2+1][0] = t4[2]; Bl[nf2+1][1] = t4[3];
                }
            }
#pragma unroll
            for (int mf = 0; mf < 2; mf++)
#pragma unroll
                for (int nf = 0; nf < 4; nf++) {
                    if (nf < nfrags) {
                        mma16816(acc[mf][nf], Ah[mf], Bh[nf]);
                        mma16816(acc[mf][nf], Ah[mf], Bl[nf]);
                        mma16816(acc[mf][nf], Al[mf], Bh[nf]);
                    }
                }
        }
        if (c + 1 < nch) cpa_wait0();
        __syncthreads();
    }

    int g = lane >> 2, tig = lane & 3;
    int b = m0 / Mimg;
    int base = m0 - b * Mimg;
    float* ob = out + (size_t)b * Cout * Mimg;
#pragma unroll
    for (int mf = 0; mf < 2; mf++) {
        int p1 = base + wm*32 + mf*16 + g;
        int p2 = p1 + 8;
#pragma unroll
        for (int nf = 0; nf < 4; nf++) {
            if (nf < nfrags) {
                int n0 = ocb + wn*warpN + nf*8 + 2*tig;
                float b0 = bias ? bias[n0] : 0.f;
                float b1 = bias ? bias[n0+1] : 0.f;
                float v00 = acc[mf][nf][0] + b0, v01 = acc[mf][nf][1] + b1;
                float v10 = acc[mf][nf][2] + b0, v11 = acc[mf][nf][3] + b1;
                if (outRelu) {
                    v00 = fmaxf(v00, 0.f); v01 = fmaxf(v01, 0.f);
                    v10 = fmaxf(v10, 0.f); v11 = fmaxf(v11, 0.f);
                }
                ob[(size_t)n0*Mimg + p1]     = v00;
                ob[(size_t)(n0+1)*Mimg + p1] = v01;
                ob[(size_t)n0*Mimg + p2]     = v10;
                ob[(size_t)(n0+1)*Mimg + p2] = v11;
            }
        }
    }
}

// ---------------- warp-MMA 3x3 conv, cp.async double-buffered ----------------
__global__ void __launch_bounds__(256)
conv3x3_wmma(const __nv_bfloat16* __restrict__ sh, const __nv_bfloat16* __restrict__ sl,
             const __nv_bfloat16* __restrict__ wh, const __nv_bfloat16* __restrict__ wl,
             const float* __restrict__ bias, float* __restrict__ out,
             int Cin, int Cout, int NT, int NP)
{
    extern __shared__ char dyn[];
    unsigned sm0 = s2u(dyn);
    int tid = threadIdx.x, lane = tid & 31, warp = tid >> 5;
    int wm = warp >> 1, wn = warp & 1;
    int warpN = NT >> 1, nfrags = warpN >> 3;
    int y0 = blockIdx.x * 4, ocb = blockIdx.y * NT, b = blockIdx.z;
    int cpt = Cin >> 5;
    int nch = 9 * cpt;
    int nb = NT >> 3;
    float acc[2][4][4];
#pragma unroll
    for (int mf = 0; mf < 2; mf++)
#pragma unroll
        for (int nf = 0; nf < 4; nf++)
#pragma unroll
            for (int j = 0; j < 4; j++) acc[mf][nf][j] = 0.f;
    int sub = lane >> 3, r = lane & 7;

    auto LD = [&](int c, int bufi) {
        int tap = c / cpt, cc = c - tap*cpt;
        int ky = tap / 3, kx = tap % 3;
        size_t gbase = (size_t)kx * NP + (size_t)b * Cin + cc*32;
        unsigned base = sm0 + bufi * BUFB;
        for (int i = tid; i < 512; i += 256) {
            int ci = i >> 4, q = i & 15;
            size_t go = (gbase + ci) * 1088 + (size_t)(y0 + ky) * 32 + q*8;
            cpa16(base + ci*272 + q*16, sh + go);
            cpa16(base + AL_OFF + ci*272 + q*16, sl + go);
        }
        for (int i = tid; i < 32*nb; i += 256) {
            int ci = i / nb, q = i % nb;
            size_t wsrc = ((size_t)tap * Cin + cc*32 + ci) * Cout + ocb + q*8;
            cpa16(base + BH_OFF + ci*144 + q*16, wh + wsrc);
            cpa16(base + BL_OFF + ci*144 + q*16, wl + wsrc);
        }
    };

    LD(0, 0); cpa_commit(); cpa_wait0(); __syncthreads();
    for (int c = 0; c < nch; c++) {
        int bi = c & 1;
        if (c + 1 < nch) { LD(c + 1, bi ^ 1); cpa_commit(); }
        unsigned aHb = sm0 + bi*BUFB, aLb = aHb + AL_OFF, bHb = aHb + BH_OFF, bLb = aHb + BL_OFF;
#pragma unroll
        for (int kf = 0; kf < 2; kf++) {
            unsigned Ah[2][4], Al[2][4];
            int akrow = kf*16 + ((sub & 2) ? 8 : 0) + r;
            int acoff = (sub & 1) ? 8 : 0;
#pragma unroll
            for (int mf = 0; mf < 2; mf++) {
                unsigned off = (unsigned)(akrow*272 + (wm*32 + mf*16 + acoff)*2);
                ldsm4t(Ah[mf], aHb + off);
                ldsm4t(Al[mf], aLb + off);
            }
            unsigned Bh[4][2], Bl[4][2];
            int bkrow = kf*16 + ((sub & 1) ? 8 : 0) + r;
            int bcoff = (sub & 2) ? 8 : 0;
#pragma unroll
            for (int nf2 = 0; nf2 < 4; nf2 += 2) {
                if (nf2 < nfrags) {
                    unsigned off = (unsigned)(bkrow*144 + (wn*warpN + nf2*8 + bcoff)*2);
                    unsigned t4[4];
                    ldsm4t(t4, bHb + off);
                    Bh[nf2][0] = t4[0]; Bh[nf2][1] = t4[1];
                    Bh[nf2+1][0] = t4[2]; Bh[nf2+1][1] = t4[3];
                    ldsm4t(t4, bLb + off);
                    Bl[nf2][0] = t4[0]; Bl[nf2][1] = t4[1];
                    Bl[nf2+1][0] = t4[2]; Bl[nf2+1][1] = t4[3];
                }
            }
#pragma unroll
            for (int mf = 0; mf < 2; mf++)
#pragma unroll
                for (int nf = 0; nf < 4; nf++) {
                    if (nf < nfrags) {
                        mma16816(acc[mf][nf], Ah[mf], Bh[nf]);
                        mma16816(acc[mf][nf], Ah[mf], Bl[nf]);
                        mma16816(acc[mf][nf], Al[mf], Bh[nf]);
                    }
                }
        }
        if (c + 1 < nch) cpa_wait0();
        __syncthreads();
    }

    int g = lane >> 2, tig = lane & 3;
    float* ob = out + (size_t)b * Cout * 1024;
#pragma unroll
    for (int mf = 0; mf < 2; mf++) {
        int m1 = wm*32 + mf*16 + g;
        int m2 = m1 + 8;
        int p1 = (y0 + (m1 >> 5))*32 + (m1 & 31);
        int p2 = (y0 + (m2 >> 5))*32 + (m2 & 31);
#pragma unroll
        for (int nf = 0; nf < 4; nf++) {
            if (nf < nfrags) {
                int n0 = ocb + wn*warpN + nf*8 + 2*tig;
                float b0 = bias ? bias[n0] : 0.f;
                float b1 = bias ? bias[n0+1] : 0.f;
                ob[(size_t)n0*1024 + p1]     = acc[mf][nf][0] + b0;
                ob[(size_t)(n0+1)*1024 + p1] = acc[mf][nf][1] + b1;
                ob[(size_t)n0*1024 + p2]     = acc[mf][nf][2] + b0;
                ob[(size_t)(n0+1)*1024 + p2] = acc[mf][nf][3] + b1;
            }
        }
    }
}

// ---------------- conv 1x1: relu(in) @ w, +bias, +res ----------------
__global__ void __launch_bounds__(256, 3)
conv1x1_f2_kernel(const float* __restrict__ in, const float* __restrict__ w,
                  const float* __restrict__ bias, const float* __restrict__ hres,
                  float* __restrict__ out, int Cin, int Cout)
{
    __shared__ ull s_w[128][16];
    int tid = threadIdx.x;
    int pos = tid & 63, ocg = tid >> 6;
    int s0 = blockIdx.x * 256 + pos * 4;
    int ocb = blockIdx.y * 32;
    int b = blockIdx.z;
    float* swf = (float*)s_w;
    for (int i = tid; i < Cin * 32; i += 256) {
        int ocl = i / Cin; int ci = i % Cin;
        swf[ci*32 + ocl] = w[(ocb + ocl)*Cin + ci];
    }
    __syncthreads();
    ull acc[4][4];
#pragma unroll
    for (int p = 0; p < 4; p++)
#pragma unroll
        for (int j = 0; j < 4; j++) acc[p][j] = 0ull;

    for (int ci = 0; ci < Cin; ci++) {
        float4 iv = *(const float4*)&in[((size_t)(b*Cin + ci) << 10) + s0];
        ull b0 = bc2(fmaxf(iv.x, 0.f)), b1 = bc2(fmaxf(iv.y, 0.f));
        ull b2 = bc2(fmaxf(iv.z, 0.f)), b3 = bc2(fmaxf(iv.w, 0.f));
        ull wr[4];
#pragma unroll
        for (int j = 0; j < 4; j++) wr[j] = s_w[ci][ocg*4 + j];
#pragma unroll
        for (int j = 0; j < 4; j++) {
            ffma2(acc[0][j], b0, wr[j]);
            ffma2(acc[1][j], b1, wr[j]);
            ffma2(acc[2][j], b2, wr[j]);
            ffma2(acc[3][j], b3, wr[j]);
        }
    }
#pragma unroll
    for (int j = 0; j < 4; j++) {
#pragma unroll
        for (int lane = 0; lane < 2; lane++) {
            int oc = ocb + ocg*8 + 2*j + lane;
            size_t base = (((size_t)b*Cout + oc) << 10) + s0;
            float bv = bias ? bias[oc] : 0.f;
            float4 hv = make_float4(0.f, 0.f, 0.f, 0.f);
            if (hres) hv = *(const float4*)&hres[base];
            float4 ov;
            ov.x = (lane ? hi32(acc[0][j]) : lo32(acc[0][j])) + bv + hv.x;
            ov.y = (lane ? hi32(acc[1][j]) : lo32(acc[1][j])) + bv + hv.y;
            ov.z = (lane ? hi32(acc[2][j]) : lo32(acc[2][j])) + bv + hv.z;
            ov.w = (lane ? hi32(acc[3][j]) : lo32(acc[3][j])) + bv + hv.w;
            *(float4*)&out[base] = ov;
        }
    }
}

// ---------------- vector quantizer ----------------
__global__ void vq_kernel(const float* __restrict__ z, const float* __restrict__ cb,
                          float* __restrict__ qc, int* __restrict__ hist,
                          float* __restrict__ ssep)
{
    __shared__ ull s_cb[128][32];
    __shared__ float s_cn[128];
    __shared__ int s_hist[512];
    __shared__ float s_red[128];
    int tid = threadIdx.x;
    for (int i = tid; i < 512; i += 128) s_hist[i] = 0;

    int n = blockIdx.x * 128 + tid;
    int b = n >> 10, s = n & 1023;
    ull zp[32];
    float zv[64];
#pragma unroll
    for (int d = 0; d < 64; d++) zv[d] = z[(((size_t)b * 64 + d) << 10) + s];
#pragma unroll
    for (int j = 0; j < 32; j++) zp[j] = pack2(zv[2*j], zv[2*j+1]);

    const ull* cbu = (const ull*)cb;
    float best = 3.4e38f; int bi = 0;
    for (int k0 = 0; k0 < 512; k0 += 128) {
        __syncthreads();
        for (int i = tid; i < 128*32; i += 128)
            s_cb[i >> 5][i & 31] = cbu[((size_t)k0 << 5) + i];
        __syncthreads();
        {
            float cn = 0.f;
#pragma unroll
            for (int j = 0; j < 32; j++) {
                ull p = s_cb[tid][j];
                float a = lo32(p), bb = hi32(p);
                cn += a*a + bb*bb;
            }
            s_cn[tid] = cn;
        }
        __syncthreads();
        for (int k = 0; k < 128; k++) {
            ull dp = 0ull;
#pragma unroll
            for (int j = 0; j < 32; j++) ffma2(dp, zp[j], s_cb[k][j]);
            float dot = lo32(dp) + hi32(dp);
            float dd = s_cn[k] - 2.f * dot;
            if (dd < best) { best = dd; bi = k0 + k; }
        }
    }
    float sq = 0.f;
    const float* c = cb + ((size_t)bi << 6);
#pragma unroll
    for (int d = 0; d < 64; d++) {
        float cv = c[d];
        qc[(((size_t)b * 64 + d) << 10) + s] = cv;
        float df = cv - zv[d];
        sq += df * df;
    }
    atomicAdd(&s_hist[bi], 1);
    s_red[tid] = sq;
    __syncthreads();
    for (int st = 64; st > 0; st >>= 1) {
        if (tid < st) s_red[tid] += s_red[tid + st];
        __syncthreads();
    }
    if (tid == 0) ssep[blockIdx.x] = s_red[0];
    for (int i = tid; i < 512; i += 128)
        if (s_hist[i]) atomicAdd(&hist[i], s_hist[i]);
}

// ---------------- dt1: convT k=4 s=2 p=1 packed ----------------
__global__ void __launch_bounds__(256, 2)
convt_f2_kernel(const float* __restrict__ in, const float* __restrict__ w,
                const float* __restrict__ bias, float* __restrict__ out,
                int Cin, int Cout)
{
    __shared__ float s_in[8][10][21];
    __shared__ ull s_w[8][16][16];
    int tid = threadIdx.x;
    int pos = tid & 31, ocg = tid >> 5;
    int posx = pos & 3, posy = pos >> 2;
    int col0 = posx * 8, row0 = posy * 2;
    int tx = blockIdx.x & 1, ty = blockIdx.x >> 1;
    int cx0 = tx * 32, ry0 = ty * 16;
    int ocb = blockIdx.y * 32;
    int b = blockIdx.z;
    ull acc[2][8][2];
#pragma unroll
    for (int r = 0; r < 2; r++)
#pragma unroll
        for (int c = 0; c < 8; c++)
#pragma unroll
            for (int j = 0; j < 2; j++) acc[r][c][j] = 0ull;

    float* swf = (float*)s_w;
    for (int c0 = 0; c0 < Cin; c0 += 8) {
        for (int i = tid; i < 8*10*18; i += 256) {
            int ci = i / 180; int rr = (i / 18) % 10; int cc = i % 18;
            int gy = (ry0 >> 1) - 1 + rr, gx = (cx0 >> 1) - 1 + cc;
            float v = 0.f;
            if ((unsigned)gy < 32u && (unsigned)gx < 32u)
                v = fmaxf(in[((b*Cin + c0 + ci)*32 + gy)*32 + gx], 0.f);
            s_in[ci][rr][cc] = v;
        }
        for (int i = tid; i < 32*128; i += 256) {
            int ocl = i >> 7; int t = i & 127; int ci = t >> 4; int k = t & 15;
            swf[(ci*16 + k)*32 + ocl] = w[((size_t)(ocb + ocl)*Cin + c0 + ci)*16 + k];
        }
        __syncthreads();
#pragma unroll
        for (int ci = 0; ci < 8; ci++) {
            ull vb[3][6];
#pragma unroll
            for (int rr = 0; rr < 3; rr++)
#pragma unroll
                for (int cc = 0; cc < 6; cc++)
                    vb[rr][cc] = bc2(s_in[ci][posy + rr][posx*4 + cc]);
#pragma unroll
            for (int r = 0; r < 2; r++) {
#pragma unroll
                for (int kxp = 0; kxp < 2; kxp++) {
                    ull wr[4][2];
                    int t0 = r*4 + kxp, t2 = (r+2)*4 + kxp;
#pragma unroll
                    for (int j = 0; j < 2; j++) {
                        wr[0][j] = s_w[ci][t0][ocg*2 + j];
                        wr[1][j] = s_w[ci][t0+2][ocg*2 + j];
                        wr[2][j] = s_w[ci][t2][ocg*2 + j];
                        wr[3][j] = s_w[ci][t2+2][ocg*2 + j];
                    }
#pragma unroll
                    for (int cs = 0; cs < 4; cs++) {
                        int c = 2*cs + kxp;
                        int cq = cs + kxp;
#pragma unroll
                        for (int j = 0; j < 2; j++) {
                            ffma2(acc[r][c][j], vb[r][cq],     wr[0][j]);
                            ffma2(acc[r][c][j], vb[r][cq+1],   wr[1][j]);
                            ffma2(acc[r][c][j], vb[r+1][cq],   wr[2][j]);
                            ffma2(acc[r][c][j], vb[r+1][cq+1], wr[3][j]);
                        }
                    }
                }
            }
        }
        __syncthreads();
    }
#pragma unroll
    for (int r = 0; r < 2; r++)
#pragma unroll
        for (int c = 0; c < 8; c++)
#pragma unroll
            for (int j = 0; j < 2; j++) {
                int oc = ocb + ocg*4 + 2*j;
                int oy = ry0 + row0 + r, ox = cx0 + col0 + c;
                float v0 = fmaxf(lo32(acc[r][c][j]) + bias[oc], 0.f);
                float v1 = fmaxf(hi32(acc[r][c][j]) + bias[oc+1], 0.f);
                out[(((size_t)b*Cout + oc)*64 + oy)*64 + ox] = v0;
                out[(((size_t)b*Cout + oc+1)*64 + oy)*64 + ox] = v1;
            }
}

// ---------------- dt2: convT (64->3), 4-oc ----------------
__global__ void convt4s2_kernel(const float* __restrict__ in, const float* __restrict__ w,
                                const float* __restrict__ bias, float* __restrict__ out,
                                int Cin, int Hin, int Win, int Cout, int inRelu, int outRelu)
{
    __shared__ float s_in[8][10][12];
    __shared__ float s_w[4][8][16];
    int tid = threadIdx.x;
    int Hout = Hin * 2, Wout = Win * 2;
    int ntx = Wout >> 4;
    int ox0 = (blockIdx.x % ntx) << 4, oy0 = (blockIdx.x / ntx) << 4;
    int b = blockIdx.z;
    int px = tid & 15, py = tid >> 4;
    int iy0 = oy0 >> 1, ix0 = ox0 >> 1;
    float acc[4];
#pragma unroll
    for (int i = 0; i < 4; i++) acc[i] = 0.f;

    for (int c0 = 0; c0 < Cin; c0 += 8) {
        for (int i = tid; i < 8 * 10 * 10; i += 256) {
            int ci = i / 100; int rr = (i / 10) % 10; int col = i % 10;
            int gy = iy0 - 1 + rr, gx = ix0 - 1 + col;
            float v = 0.f;
            if ((unsigned)gy < (unsigned)Hin && (unsigned)gx < (unsigned)Win)
                v = in[((b*Cin + c0 + ci)*Hin + gy)*Win + gx];
            if (inRelu) v = fmaxf(v, 0.f);
            s_in[ci][rr][col] = v;
        }
        for (int i = tid; i < 4 * 8 * 16; i += 256) {
            int oc = i >> 7; int ci = (i >> 4) & 7; int k = i & 15;
            s_w[oc][ci][k] = (oc < Cout) ? w[((size_t)oc * Cin + c0 + ci)*16 + k] : 0.f;
        }
        __syncthreads();
        int ky0 = py & 1, kx0 = px & 1;
        int r0 = (py + ky0) >> 1;
        int q0 = (px + kx0) >> 1;
#pragma unroll
        for (int ci = 0; ci < 8; ci++) {
            float v00 = s_in[ci][r0][q0];
            float v01 = s_in[ci][r0][q0 + 1];
            float v10 = s_in[ci][r0 + 1][q0];
            float v11 = s_in[ci][r0 + 1][q0 + 1];
#pragma unroll
            for (int oc = 0; oc < 4; oc++) {
                float a = acc[oc];
                a += v00 * s_w[oc][ci][ky0*4 + kx0];
                a += v01 * s_w[oc][ci][ky0*4 + kx0 + 2];
                a += v10 * s_w[oc][ci][(ky0+2)*4 + kx0];
                a += v11 * s_w[oc][ci][(ky0+2)*4 + kx0 + 2];
                acc[oc] = a;
            }
        }
        __syncthreads();
    }
#pragma unroll
    for (int oc = 0; oc < 4; oc++) {
        if (oc < Cout) {
            float r = acc[oc] + bias[oc];
            if (outRelu) r = fmaxf(r, 0.f);
            out[(((size_t)b * Cout + oc)*Hout + oy0 + py)*Wout + ox0 + px] = r;
        }
    }
}

// ---------------- finalize ----------------
__global__ void finalize_kernel(const int* __restrict__ hist, const float* __restrict__ ssep,
                                float* __restrict__ out, int lastIdx)
{
    __shared__ float red[512];
    __shared__ float red2[256];
    int t = threadIdx.x;
    float p = hist[t] * (1.0f / 32768.0f);
    red[t] = p * logf(p + 1e-10f);
    if (t < 256) red2[t] = ssep[t];
    __syncthreads();
    for (int st = 256; st > 0; st >>= 1) {
        if (t < st) red[t] += red[t + st];
        __syncthreads();
    }
    for (int st = 128; st > 0; st >>= 1) {
        if (t < st) red2[t] += red2[t + st];
        __syncthreads();
    }
    if (t == 0) {
        out[0] = red2[0] * 1.25f / (32768.0f * 64.0f);
        out[lastIdx] = expf(-red[0]);
    }
}

// ---------------- launch ----------------
extern "C" void kernel_launch(void* const* d_in, const int* in_sizes, int n_in,
                              void* d_out, int out_size)
{
    const float* x     = (const float*)d_in[0];
    const float* e_w1  = (const float*)d_in[1];
    const float* e_b1  = (const float*)d_in[2];
    const float* e_w2  = (const float*)d_in[3];
    const float* e_b2  = (const float*)d_in[4];
    const float* e_w3  = (const float*)d_in[5];
    const float* e_b3  = (const float*)d_in[6];
    const float* e_r1a = (const float*)d_in[7];
    const float* e_r1b = (const float*)d_in[8];
    const float* e_r2a = (const float*)d_in[9];
    const float* e_r2b = (const float*)d_in[10];
    const float* pre_w = (const float*)d_in[11];
    const float* pre_b = (const float*)d_in[12];
    const float* cb    = (const float*)d_in[13];
    const float* d_w1  = (const float*)d_in[14];
    const float* d_b1  = (const float*)d_in[15];
    const float* d_r1a = (const float*)d_in[16];
    const float* d_r1b = (const float*)d_in[17];
    const float* d_r2a = (const float*)d_in[18];
    const float* d_r2b = (const float*)d_in[19];
    const float* dt_w1 = (const float*)d_in[20];
    const float* dt_b1 = (const float*)d_in[21];
    const float* dt_w2 = (const float*)d_in[22];
    const float* dt_b2 = (const float*)d_in[23];
    float* out = (float*)d_out;

    float *A, *Bb, *C, *R, *Z, *Q, *ssep; int* hist;
    __nv_bfloat16 *Sh, *Sl, *Gh, *Gl, *Wh, *Wl;
    cudaGetSymbolAddress((void**)&A,    g_A);
    cudaGetSymbolAddress((void**)&Bb,   g_B);
    cudaGetSymbolAddress((void**)&C,    g_C);
    cudaGetSymbolAddress((void**)&R,    g_R);
    cudaGetSymbolAddress((void**)&Z,    g_Z);
    cudaGetSymbolAddress((void**)&Q,    g_Q);
    cudaGetSymbolAddress((void**)&ssep, g_ssep);
    cudaGetSymbolAddress((void**)&hist, g_hist);
    cudaGetSymbolAddress((void**)&Sh,   g_Sh);
    cudaGetSymbolAddress((void**)&Sl,   g_Sl);
    cudaGetSymbolAddress((void**)&Gh,   g_Gh);
    cudaGetSymbolAddress((void**)&Gl,   g_Gl);
    cudaGetSymbolAddress((void**)&Wh,   g_Wh);
    cudaGetSymbolAddress((void**)&Wl,   g_Wl);

    static int smem_set = 0;
    if (!smem_set) {
        cudaFuncSetAttribute(gemm_wmma, cudaFuncAttributeMaxDynamicSharedMemorySize, DYN_SMEM);
        cudaFuncSetAttribute(conv3x3_wmma, cudaFuncAttributeMaxDynamicSharedMemorySize, DYN_SMEM);
        smem_set = 1;
    }

    zero_kernel<<<2, 256>>>(hist);

    // ---- encoder ----
    // conv1: 3->64, k4s2, out 64x64, relu (K=64, M=32*4096)
    stage_w_gen<<<16, 256>>>(e_w1, Wh, Wl, 3, 4, 64, 16);
    stage_im2col<<<dim3(64, 8), 256>>>(x, Gh, Gl, 3, 4, 128, 128, 4, 2, 1, 64, 64, BATCH*4096);
    gemm_wmma<<<dim3(1024, 1), 256, DYN_SMEM>>>(Gh, Gl, Wh, Wl, e_b1, A, 64, 64, 64, BATCH*4096, 4096, 1);
    // conv2: 64->128, k4s2, out 32x32, relu (K=1024, M=32*1024), read-once stager
    stage_w_gen<<<128, 256>>>(e_w2, Wh, Wl, 64, 64, 128, 16);
    stage_k4s2<<<2048, 256>>>(A, Gh, Gl, BATCH*1024);
    gemm_wmma<<<dim3(256, 2), 256, DYN_SMEM>>>(Gh, Gl, Wh, Wl, e_b2, Bb, 1024, 128, 64, BATCH*1024, 1024, 1);

    // e3: 128->128 via shifted-plane wmma
    stage_w_kernel<<<64, 256>>>(e_w3, Wh, Wl, 128, 128);
    stage_in_kernel<<<4096, 256>>>(Bb, Sh, Sl, 4096, 0);
    conv3x3_wmma<<<dim3(8, 2, BATCH), 256, DYN_SMEM>>>(Sh, Sl, Wh, Wl, e_b3, C, 128, 128, 64, 4096);
    // res1
    stage_w_kernel<<<64, 256>>>(e_r1a, Wh, Wl, 128, 32);
    stage_in_kernel<<<4096, 256>>>(C, Sh, Sl, 4096, 1);
    conv3x3_wmma<<<dim3(8, 1, BATCH), 256, DYN_SMEM>>>(Sh, Sl, Wh, Wl, nullptr, R, 128, 32, 32, 4096);
    conv1x1_f2_kernel<<<dim3(4, 4, BATCH), 256>>>(R, e_r1b, nullptr, C, C, 32, 128);
    // res2
    stage_w_kernel<<<64, 256>>>(e_r2a, Wh, Wl, 128, 32);
    stage_in_kernel<<<4096, 256>>>(C, Sh, Sl, 4096, 1);
    conv3x3_wmma<<<dim3(8, 1, BATCH), 256, DYN_SMEM>>>(Sh, Sl, Wh, Wl, nullptr, R, 128, 32, 32, 4096);
    conv1x1_f2_kernel<<<dim3(4, 4, BATCH), 256>>>(R, e_r2b, nullptr, C, C, 32, 128);
    // pre-VQ 1x1
    conv1x1_f2_kernel<<<dim3(4, 2, BATCH), 256>>>(C, pre_w, pre_b, nullptr, Z, 128, 64);

    // ---- VQ ----
    vq_kernel<<<256, 128>>>(Z, cb, Q, hist, ssep);

    // ---- decoder ----
    stage_w_kernel<<<64, 256>>>(d_w1, Wh, Wl, 64, 128);
    stage_in_kernel<<<2048, 256>>>(Q, Sh, Sl, 2048, 0);
    conv3x3_wmma<<<dim3(8, 2, BATCH), 256, DYN_SMEM>>>(Sh, Sl, Wh, Wl, d_b1, Bb, 64, 128, 64, 2048);
    stage_w_kernel<<<64, 256>>>(d_r1a, Wh, Wl, 128, 32);
    stage_in_kernel<<<4096, 256>>>(Bb, Sh, Sl, 4096, 1);
    conv3x3_wmma<<<dim3(8, 1, BATCH), 256, DYN_SMEM>>>(Sh, Sl, Wh, Wl, nullptr, R, 128, 32, 32, 4096);
    conv1x1_f2_kernel<<<dim3(4, 4, BATCH), 256>>>(R, d_r1b, nullptr, Bb, Bb, 32, 128);
    stage_w_kernel<<<64, 256>>>(d_r2a, Wh, Wl, 128, 32);
    stage_in_kernel<<<4096, 256>>>(Bb, Sh, Sl, 4096, 1);
    conv3x3_wmma<<<dim3(8, 1, BATCH), 256, DYN_SMEM>>>(Sh, Sl, Wh, Wl, nullptr, R, 128, 32, 32, 4096);
    conv1x1_f2_kernel<<<dim3(4, 4, BATCH), 256>>>(R, d_r2b, nullptr, Bb, Bb, 32, 128);
    convt_f2_kernel<<<dim3(8, 2, BATCH), 256>>>(Bb, dt_w1, dt_b1, A, 128, 64);
    convt4s2_kernel<<<dim3(64, 1, BATCH), 256>>>(A, dt_w2, dt_b2, out + 1, 64, 64, 64, 3, 0, 0);

    finalize_kernel<<<1, 512>>>(hist, ssep, out, out_size - 1);
}

// round 12
// speedup vs baseline: 1.4367x; 1.2141x over previous
#include <cuda_runtime.h>
#include <cuda_bf16.h>
#include <math.h>

typedef unsigned long long ull;

// ---------------- packed f32x2 helpers (scalar kernels) ----------------
__device__ __forceinline__ ull pack2(float lo, float hi) {
    ull r; asm("mov.b64 %0, {%1, %2};" : "=l"(r) : "f"(lo), "f"(hi)); return r;
}
__device__ __forceinline__ ull bc2(float v) { return pack2(v, v); }
__device__ __forceinline__ void ffma2(ull& d, ull a, ull b) {
    asm("fma.rn.f32x2 %0, %1, %2, %0;" : "+l"(d) : "l"(a), "l"(b));
}
__device__ __forceinline__ float lo32(ull v) { return __uint_as_float((unsigned)v); }
__device__ __forceinline__ float hi32(ull v) { return __uint_as_float((unsigned)(v >> 32)); }

// ---------------- mma.sync / cp.async helpers ----------------
__device__ __forceinline__ unsigned s2u(const void* p) {
    unsigned a; asm("{ .reg .u64 t; cvta.to.shared.u64 t, %1; cvt.u32.u64 %0, t; }" : "=r"(a) : "l"(p));
    return a;
}
__device__ __forceinline__ void ldsm4t(unsigned* r, unsigned addr) {
    asm volatile("ldmatrix.sync.aligned.m8n8.x4.trans.shared.b16 {%0,%1,%2,%3}, [%4];"
                 : "=r"(r[0]), "=r"(r[1]), "=r"(r[2]), "=r"(r[3]) : "r"(addr));
}
__device__ __forceinline__ void mma16816(float* c, const unsigned* a, const unsigned* b) {
    asm volatile(
        "mma.sync.aligned.m16n8k16.row.col.f32.bf16.bf16.f32 "
        "{%0,%1,%2,%3}, {%4,%5,%6,%7}, {%8,%9}, {%0,%1,%2,%3};"
        : "+f"(c[0]), "+f"(c[1]), "+f"(c[2]), "+f"(c[3])
        : "r"(a[0]), "r"(a[1]), "r"(a[2]), "r"(a[3]), "r"(b[0]), "r"(b[1]));
}
__device__ __forceinline__ void cpa16(unsigned saddr, const void* g) {
    asm volatile("cp.async.cg.shared.global [%0], [%1], 16;" :: "r"(saddr), "l"(g));
}
__device__ __forceinline__ void cpa_commit() { asm volatile("cp.async.commit_group;" ::: "memory"); }
__device__ __forceinline__ void cpa_wait0() { asm volatile("cp.async.wait_group 0;" ::: "memory"); }
__device__ __forceinline__ void cpa_wait1() { asm volatile("cp.async.wait_group 1;" ::: "memory"); }

// smem stage layout (bytes): Ah[32x136] Al Bh[32x72] Bl; 3 stages
#define BUFB 26624
#define AL_OFF 8704
#define BH_OFF 17408
#define BL_OFF 22016
#define DYN_SMEM (3*26624)

// ---------------- scratch ----------------
#define BATCH 32
__device__ float g_A[BATCH*64*64*64];
__device__ float g_B[BATCH*128*32*32];
__device__ float g_C[BATCH*128*32*32];
__device__ float g_R[BATCH*32*32*32];
__device__ float g_Z[BATCH*64*32*32];
__device__ float g_Q[BATCH*64*32*32];
__device__ int   g_hist[512];
__device__ float g_ssep[256];
__device__ __align__(16) __nv_bfloat16 g_Sh[3*4096*1088];
__device__ __align__(16) __nv_bfloat16 g_Sl[3*4096*1088];
__device__ __align__(16) __nv_bfloat16 g_Gh[1024*32768];
__device__ __align__(16) __nv_bfloat16 g_Gl[1024*32768];
__device__ __align__(16) __nv_bfloat16 g_Wh[9*128*128];
__device__ __align__(16) __nv_bfloat16 g_Wl[9*128*128];

__global__ void zero_kernel(int* hist) {
    int t = blockIdx.x * blockDim.x + threadIdx.x;
    if (t < 512) hist[t] = 0;
}

// ---------------- stage input (shifted planes) ----------------
__global__ void stage_in_kernel(const float* __restrict__ in, __nv_bfloat16* __restrict__ sh,
                                __nv_bfloat16* __restrict__ sl, int NP, int doRelu)
{
    int plane = blockIdx.x;
    const float* src = in + (size_t)plane * 1024;
    for (int i = threadIdx.x; i < 3*1088; i += 256) {
        int kx = i / 1088; int r = (i % 1088) / 32; int c = i & 31;
        float v = 0.f;
        int sy = r - 1, sx = c + kx - 1;
        if ((unsigned)sy < 32u && (unsigned)sx < 32u) v = src[sy*32 + sx];
        if (doRelu) v = fmaxf(v, 0.f);
        __nv_bfloat16 h = __float2bfloat16(v);
        __nv_bfloat16 l = __float2bfloat16(v - __bfloat162float(h));
        size_t o = ((size_t)kx * NP + plane) * 1088 + r*32 + c;
        sh[o] = h; sl[o] = l;
    }
}

// ---------------- stage weights (3x3: [tap][ci][oc]) ----------------
__global__ void stage_w_kernel(const float* __restrict__ w, __nv_bfloat16* __restrict__ wh,
                               __nv_bfloat16* __restrict__ wl, int Cin, int Cout)
{
    int n = Cin * Cout * 9;
    for (int i = blockIdx.x*256 + threadIdx.x; i < n; i += gridDim.x*256) {
        int oc = i / (Cin*9); int rr = i % (Cin*9); int ci = rr / 9; int t = rr % 9;
        float v = w[i];
        __nv_bfloat16 h = __float2bfloat16(v);
        __nv_bfloat16 l = __float2bfloat16(v - __bfloat162float(h));
        size_t dst = ((size_t)t * Cin + ci) * Cout + oc;
        wh[dst] = h; wl[dst] = l;
    }
}

// ---------------- dt1 weight stage: [parity][tap][ci][oc], ky=2*tyi+py, kx=2*txi+px ----------------
__global__ void stage_w_dt1(const float* __restrict__ w, __nv_bfloat16* __restrict__ wh,
                            __nv_bfloat16* __restrict__ wl)
{
    for (int i = blockIdx.x*256 + threadIdx.x; i < 4*4*128*64; i += gridDim.x*256) {
        int oc = i & 63, ci = (i >> 6) & 127, t = (i >> 13) & 3, p = i >> 15;
        int ky = 2*(t >> 1) + (p >> 1);
        int kx = 2*(t & 1) + (p & 1);
        float v = w[((size_t)oc*128 + ci)*16 + ky*4 + kx];
        __nv_bfloat16 h = __float2bfloat16(v);
        __nv_bfloat16 l = __float2bfloat16(v - __bfloat162float(h));
        wh[i] = h; wl[i] = l;
    }
}

// ---------------- generic im2col stage (conv1) ----------------
__global__ void stage_im2col(const float* __restrict__ in, __nv_bfloat16* __restrict__ ah,
                             __nv_bfloat16* __restrict__ al,
                             int Cin, int CinP, int Hin, int Win, int KW,
                             int stride, int pad, int Hout, int Wout, int Mtot)
{
    int k = blockIdx.x;
    int t = k / CinP, ci = k % CinP;
    int ky = t / KW, kx = t % KW;
    int Mimg = Hout * Wout;
    __nv_bfloat16* dh = ah + (size_t)k * Mtot;
    __nv_bfloat16* dl = al + (size_t)k * Mtot;
    int seg = Mtot / gridDim.y;
    int mend = seg * (blockIdx.y + 1);
    for (int m = seg * blockIdx.y + threadIdx.x; m < mend; m += 256) {
        int b = m / Mimg, pos = m % Mimg;
        int y = pos / Wout, x = pos % Wout;
        float v = 0.f;
        if (ci < Cin) {
            int iy = y*stride - pad + ky, ix = x*stride - pad + kx;
            if ((unsigned)iy < (unsigned)Hin && (unsigned)ix < (unsigned)Win)
                v = in[((size_t)(b*Cin + ci)*Hin + iy)*Win + ix];
        }
        __nv_bfloat16 h = __float2bfloat16(v);
        __nv_bfloat16 l = __float2bfloat16(v - __bfloat162float(h));
        dh[m] = h; dl[m] = l;
    }
}

// ---------------- read-once tiled im2col for conv2 ----------------
__global__ void stage_k4s2(const float* __restrict__ in, __nv_bfloat16* __restrict__ gh,
                           __nv_bfloat16* __restrict__ gl, int Mtot)
{
    __shared__ float tile[67][68];
    int bci = blockIdx.x;
    const float* src = in + (size_t)bci * 4096;
    for (int i = threadIdx.x; i < 67*67; i += 256) {
        int r = i / 67, c = i % 67;
        float v = 0.f;
        int iy = r - 1, ix = c - 1;
        if ((unsigned)iy < 64u && (unsigned)ix < 64u) v = src[iy*64 + ix];
        tile[r][c] = v;
    }
    __syncthreads();
    int b = bci >> 6, ci = bci & 63;
    for (int i = threadIdx.x; i < 16*1024; i += 256) {
        int t = i >> 10, pos = i & 1023;
        int y = pos >> 5, x = pos & 31;
        int ky = t >> 2, kx = t & 3;
        float v = tile[2*y + ky][2*x + kx];
        __nv_bfloat16 h = __float2bfloat16(v);
        __nv_bfloat16 l = __float2bfloat16(v - __bfloat162float(h));
        size_t dst = ((size_t)(t*64 + ci)) * Mtot + (size_t)b*1024 + pos;
        gh[dst] = h; gl[dst] = l;
    }
}

// ---------------- generic weight stage: W[k][oc], OIHW source ----------------
__global__ void stage_w_gen(const float* __restrict__ w, __nv_bfloat16* __restrict__ wh,
                            __nv_bfloat16* __restrict__ wl,
                            int Cin, int CinP, int Cout, int T)
{
    int K = T * CinP;
    int ntot = K * Cout;
    for (int i = blockIdx.x*256 + threadIdx.x; i < ntot; i += gridDim.x*256) {
        int k = i / Cout, oc = i % Cout;
        int t = k / CinP, ci = k % CinP;
        float v = (ci < Cin) ? w[((size_t)oc*Cin + ci)*T + t] : 0.f;
        __nv_bfloat16 h = __float2bfloat16(v);
        __nv_bfloat16 l = __float2bfloat16(v - __bfloat162float(h));
        wh[(size_t)k*Cout + oc] = h; wl[(size_t)k*Cout + oc] = l;
    }
}

// ---------------- MMA core macro body (shared by all 3 wmma kernels) ----------------
#define MMA_BODY(aHb, aLb, bHb, bLb)                                              \
    _Pragma("unroll")                                                             \
    for (int kf = 0; kf < 2; kf++) {                                              \
        unsigned Ah[2][4], Al[2][4];                                              \
        int akrow = kf*16 + ((sub & 2) ? 8 : 0) + r;                              \
        int acoff = (sub & 1) ? 8 : 0;                                            \
        _Pragma("unroll")                                                         \
        for (int mf = 0; mf < 2; mf++) {                                          \
            unsigned off = (unsigned)(akrow*272 + (wm*32 + mf*16 + acoff)*2);     \
            ldsm4t(Ah[mf], (aHb) + off);                                          \
            ldsm4t(Al[mf], (aLb) + off);                                          \
        }                                                                         \
        unsigned Bh[4][2], Bl[4][2];                                              \
        int bkrow = kf*16 + ((sub & 1) ? 8 : 0) + r;                              \
        int bcoff = (sub & 2) ? 8 : 0;                                            \
        _Pragma("unroll")                                                         \
        for (int nf2 = 0; nf2 < 4; nf2 += 2) {                                    \
            if (nf2 < nfrags) {                                                   \
                unsigned off = (unsigned)(bkrow*144 + (wn*warpN + nf2*8 + bcoff)*2); \
                unsigned t4[4];                                                   \
                ldsm4t(t4, (bHb) + off);                                          \
                Bh[nf2][0] = t4[0]; Bh[nf2][1] = t4[1];                           \
                Bh[nf2+1][0] = t4[2]; Bh[nf2+1][1] = t4[3];                       \
                ldsm4t(t4, (bLb) + off);                                          \
                Bl[nf2][0] = t4[0]; Bl[nf2][1] = t4[1];                           \
                Bl[nf2+1][0] = t4[2]; Bl[nf2+1][1] = t4[3];                       \
            }                                                                     \
        }                                                                         \
        _Pragma("unroll")                                                         \
        for (int mf = 0; mf < 2; mf++)                                            \
            _Pragma("unroll")                                                     \
            for (int nf = 0; nf < 4; nf++) {                                      \
                if (nf < nfrags) {                                                \
                    mma16816(acc[mf][nf], Ah[mf], Bh[nf]);                        \
                    mma16816(acc[mf][nf], Ah[mf], Bl[nf]);                        \
                    mma16816(acc[mf][nf], Al[mf], Bh[nf]);                        \
                }                                                                 \
            }                                                                     \
    }

// ---------------- generic GEMM, 3-stage cp.async pipeline ----------------
__global__ void __launch_bounds__(256)
gemm_wmma(const __nv_bfloat16* __restrict__ ah, const __nv_bfloat16* __restrict__ al,
          const __nv_bfloat16* __restrict__ wh, const __nv_bfloat16* __restrict__ wl,
          const float* __restrict__ bias, float* __restrict__ out,
          int K, int Cout, int NT, int Mtot, int Mimg, int outRelu)
{
    extern __shared__ char dyn[];
    unsigned sm0 = s2u(dyn);
    int tid = threadIdx.x, lane = tid & 31, warp = tid >> 5;
    int wm = warp >> 1, wn = warp & 1;
    int warpN = NT >> 1, nfrags = warpN >> 3;
    int m0 = blockIdx.x * 128, ocb = blockIdx.y * NT;
    int nb = NT >> 3;
    int nch = K >> 5;
    float acc[2][4][4];
#pragma unroll
    for (int mf = 0; mf < 2; mf++)
#pragma unroll
        for (int nf = 0; nf < 4; nf++)
#pragma unroll
            for (int j = 0; j < 4; j++) acc[mf][nf][j] = 0.f;
    int sub = lane >> 3, r = lane & 7;

    auto LD = [&](int c) {
        int kc = c << 5;
        unsigned base = sm0 + (c % 3) * BUFB;
        for (int i = tid; i < 512; i += 256) {
            int kk = i >> 4, q = i & 15;
            size_t go = (size_t)(kc + kk) * Mtot + m0 + q*8;
            cpa16(base + kk*272 + q*16, ah + go);
            cpa16(base + AL_OFF + kk*272 + q*16, al + go);
        }
        for (int i = tid; i < 32*nb; i += 256) {
            int kk = i / nb, q = i % nb;
            size_t wsrc = (size_t)(kc + kk) * Cout + ocb + q*8;
            cpa16(base + BH_OFF + kk*144 + q*16, wh + wsrc);
            cpa16(base + BL_OFF + kk*144 + q*16, wl + wsrc);
        }
    };

    LD(0); cpa_commit();
    if (nch > 1) { LD(1); cpa_commit(); }
    for (int c = 0; c < nch; c++) {
        if (c + 1 < nch) cpa_wait1(); else cpa_wait0();
        __syncthreads();
        if (c + 2 < nch) { LD(c + 2); cpa_commit(); }
        unsigned aHb = sm0 + (c % 3)*BUFB, aLb = aHb + AL_OFF, bHb = aHb + BH_OFF, bLb = aHb + BL_OFF;
        MMA_BODY(aHb, aLb, bHb, bLb)
        __syncthreads();
    }

    int g = lane >> 2, tig = lane & 3;
    int b = m0 / Mimg;
    int base = m0 - b * Mimg;
    float* ob = out + (size_t)b * Cout * Mimg;
#pragma unroll
    for (int mf = 0; mf < 2; mf++) {
        int p1 = base + wm*32 + mf*16 + g;
        int p2 = p1 + 8;
#pragma unroll
        for (int nf = 0; nf < 4; nf++) {
            if (nf < nfrags) {
                int n0 = ocb + wn*warpN + nf*8 + 2*tig;
                float b0 = bias ? bias[n0] : 0.f;
                float b1 = bias ? bias[n0+1] : 0.f;
                float v00 = acc[mf][nf][0] + b0, v01 = acc[mf][nf][1] + b1;
                float v10 = acc[mf][nf][2] + b0, v11 = acc[mf][nf][3] + b1;
                if (outRelu) {
                    v00 = fmaxf(v00, 0.f); v01 = fmaxf(v01, 0.f);
                    v10 = fmaxf(v10, 0.f); v11 = fmaxf(v11, 0.f);
                }
                ob[(size_t)n0*Mimg + p1]     = v00;
                ob[(size_t)(n0+1)*Mimg + p1] = v01;
                ob[(size_t)n0*Mimg + p2]     = v10;
                ob[(size_t)(n0+1)*Mimg + p2] = v11;
            }
        }
    }
}

// ---------------- warp-MMA 3x3 conv, 3-stage pipeline ----------------
__global__ void __launch_bounds__(256)
conv3x3_wmma(const __nv_bfloat16* __restrict__ sh, const __nv_bfloat16* __restrict__ sl,
             const __nv_bfloat16* __restrict__ wh, const __nv_bfloat16* __restrict__ wl,
             const float* __restrict__ bias, float* __restrict__ out,
             int Cin, int Cout, int NT, int NP)
{
    extern __shared__ char dyn[];
    unsigned sm0 = s2u(dyn);
    int tid = threadIdx.x, lane = tid & 31, warp = tid >> 5;
    int wm = warp >> 1, wn = warp & 1;
    int warpN = NT >> 1, nfrags = warpN >> 3;
    int y0 = blockIdx.x * 4, ocb = blockIdx.y * NT, b = blockIdx.z;
    int cpt = Cin >> 5;
    int nch = 9 * cpt;
    int nb = NT >> 3;
    float acc[2][4][4];
#pragma unroll
    for (int mf = 0; mf < 2; mf++)
#pragma unroll
        for (int nf = 0; nf < 4; nf++)
#pragma unroll
            for (int j = 0; j < 4; j++) acc[mf][nf][j] = 0.f;
    int sub = lane >> 3, r = lane & 7;

    auto LD = [&](int c) {
        int tap = c / cpt, cc = c - tap*cpt;
        int ky = tap / 3, kx = tap % 3;
        size_t gbase = (size_t)kx * NP + (size_t)b * Cin + cc*32;
        unsigned base = sm0 + (c % 3) * BUFB;
        for (int i = tid; i < 512; i += 256) {
            int ci = i >> 4, q = i & 15;
            size_t go = (gbase + ci) * 1088 + (size_t)(y0 + ky) * 32 + q*8;
            cpa16(base + ci*272 + q*16, sh + go);
            cpa16(base + AL_OFF + ci*272 + q*16, sl + go);
        }
        for (int i = tid; i < 32*nb; i += 256) {
            int ci = i / nb, q = i % nb;
            size_t wsrc = ((size_t)tap * Cin + cc*32 + ci) * Cout + ocb + q*8;
            cpa16(base + BH_OFF + ci*144 + q*16, wh + wsrc);
            cpa16(base + BL_OFF + ci*144 + q*16, wl + wsrc);
        }
    };

    LD(0); cpa_commit();
    LD(1); cpa_commit();
    for (int c = 0; c < nch; c++) {
        if (c + 1 < nch) cpa_wait1(); else cpa_wait0();
        __syncthreads();
        if (c + 2 < nch) { LD(c + 2); cpa_commit(); }
        unsigned aHb = sm0 + (c % 3)*BUFB, aLb = aHb + AL_OFF, bHb = aHb + BH_OFF, bLb = aHb + BL_OFF;
        MMA_BODY(aHb, aLb, bHb, bLb)
        __syncthreads();
    }

    int g = lane >> 2, tig = lane & 3;
    float* ob = out + (size_t)b * Cout * 1024;
#pragma unroll
    for (int mf = 0; mf < 2; mf++) {
        int m1 = wm*32 + mf*16 + g;
        int m2 = m1 + 8;
        int p1 = (y0 + (m1 >> 5))*32 + (m1 & 31);
        int p2 = (y0 + (m2 >> 5))*32 + (m2 & 31);
#pragma unroll
        for (int nf = 0; nf < 4; nf++) {
            if (nf < nfrags) {
                int n0 = ocb + wn*warpN + nf*8 + 2*tig;
                float b0 = bias ? bias[n0] : 0.f;
                float b1 = bias ? bias[n0+1] : 0.f;
                ob[(size_t)n0*1024 + p1]     = acc[mf][nf][0] + b0;
                ob[(size_t)(n0+1)*1024 + p1] = acc[mf][nf][1] + b1;
                ob[(size_t)n0*1024 + p2]     = acc[mf][nf][2] + b0;
                ob[(size_t)(n0+1)*1024 + p2] = acc[mf][nf][3] + b1;
            }
        }
    }
}

// ---------------- dt1 convT via parity GEMMs (tensor), 3-stage pipeline ----------------
// parity p=blockIdx.y: py=p>>1, px=p&1; taps t=(tyi,txi): ky=2tyi+py, dy=tyi-1+py (same x).
// Reads the SAME shifted-plane staging as conv3x3. K=4*128=512, N=64, out 64x64 (+bias+relu).
__global__ void __launch_bounds__(256)
convt_wmma(const __nv_bfloat16* __restrict__ sh, const __nv_bfloat16* __restrict__ sl,
           const __nv_bfloat16* __restrict__ wh, const __nv_bfloat16* __restrict__ wl,
           const float* __restrict__ bias, float* __restrict__ out, int NP)
{
    extern __shared__ char dyn[];
    unsigned sm0 = s2u(dyn);
    int tid = threadIdx.x, lane = tid & 31, warp = tid >> 5;
    int wm = warp >> 1, wn = warp & 1;
    const int warpN = 32, nfrags = 4, nb = 8;
    int y0 = blockIdx.x * 4, p = blockIdx.y, b = blockIdx.z;
    int py = p >> 1, px = p & 1;
    const int Cin = 128, cpt = 4, nch = 16;
    float acc[2][4][4];
#pragma unroll
    for (int mf = 0; mf < 2; mf++)
#pragma unroll
        for (int nf = 0; nf < 4; nf++)
#pragma unroll
            for (int j = 0; j < 4; j++) acc[mf][nf][j] = 0.f;
    int sub = lane >> 3, r = lane & 7;

    auto LD = [&](int c) {
        int t = c >> 2, cc = c & 3;
        int tyi = t >> 1, txi = t & 1;
        int rowoff = tyi + py;          // padded row shift (0..2)
        int plane = txi + px;           // kx-shift plane (0..2)
        size_t gbase = (size_t)plane * NP + (size_t)b * Cin + cc*32;
        unsigned base = sm0 + (c % 3) * BUFB;
        for (int i = tid; i < 512; i += 256) {
            int ci = i >> 4, q = i & 15;
            size_t go = (gbase + ci) * 1088 + (size_t)(y0 + rowoff) * 32 + q*8;
            cpa16(base + ci*272 + q*16, sh + go);
            cpa16(base + AL_OFF + ci*272 + q*16, sl + go);
        }
        for (int i = tid; i < 32*nb; i += 256) {
            int ci = i / nb, q = i % nb;
            size_t wsrc = ((size_t)(p*4 + t) * 128 + cc*32 + ci) * 64 + q*8;
            cpa16(base + BH_OFF + ci*144 + q*16, wh + wsrc);
            cpa16(base + BL_OFF + ci*144 + q*16, wl + wsrc);
        }
    };

    LD(0); cpa_commit();
    LD(1); cpa_commit();
    for (int c = 0; c < nch; c++) {
        if (c + 1 < nch) cpa_wait1(); else cpa_wait0();
        __syncthreads();
        if (c + 2 < nch) { LD(c + 2); cpa_commit(); }
        unsigned aHb = sm0 + (c % 3)*BUFB, aLb = aHb + AL_OFF, bHb = aHb + BH_OFF, bLb = aHb + BL_OFF;
        MMA_BODY(aHb, aLb, bHb, bLb)
        __syncthreads();
    }

    int g = lane >> 2, tig = lane & 3;
    float* ob = out + (size_t)b * 64 * 4096;
#pragma unroll
    for (int mf = 0; mf < 2; mf++) {
        int m1 = wm*32 + mf*16 + g;
        int m2 = m1 + 8;
#pragma unroll
        for (int mm = 0; mm < 2; mm++) {
            int m = mm ? m2 : m1;
            int y = y0 + (m >> 5), x = m & 31;
            int opix = (2*y + py)*64 + 2*x + px;
#pragma unroll
            for (int nf = 0; nf < 4; nf++) {
                int n0 = wn*warpN + nf*8 + 2*tig;
                float v0 = acc[mf][nf][mm*2 + 0] + bias[n0];
                float v1 = acc[mf][nf][mm*2 + 1] + bias[n0+1];
                ob[(size_t)n0*4096 + opix]     = fmaxf(v0, 0.f);
                ob[(size_t)(n0+1)*4096 + opix] = fmaxf(v1, 0.f);
            }
        }
    }
}

// ---------------- conv1: scalar (unused slot kept minimal) ----------------

// ---------------- conv 1x1: relu(in) @ w, +bias, +res ----------------
__global__ void __launch_bounds__(256, 3)
conv1x1_f2_kernel(const float* __restrict__ in, const float* __restrict__ w,
                  const float* __restrict__ bias, const float* __restrict__ hres,
                  float* __restrict__ out, int Cin, int Cout)
{
    __shared__ ull s_w[128][16];
    int tid = threadIdx.x;
    int pos = tid & 63, ocg = tid >> 6;
    int s0 = blockIdx.x * 256 + pos * 4;
    int ocb = blockIdx.y * 32;
    int b = blockIdx.z;
    float* swf = (float*)s_w;
    for (int i = tid; i < Cin * 32; i += 256) {
        int ocl = i / Cin; int ci = i % Cin;
        swf[ci*32 + ocl] = w[(ocb + ocl)*Cin + ci];
    }
    __syncthreads();
    ull acc[4][4];
#pragma unroll
    for (int p = 0; p < 4; p++)
#pragma unroll
        for (int j = 0; j < 4; j++) acc[p][j] = 0ull;

    for (int ci = 0; ci < Cin; ci++) {
        float4 iv = *(const float4*)&in[((size_t)(b*Cin + ci) << 10) + s0];
        ull b0 = bc2(fmaxf(iv.x, 0.f)), b1 = bc2(fmaxf(iv.y, 0.f));
        ull b2 = bc2(fmaxf(iv.z, 0.f)), b3 = bc2(fmaxf(iv.w, 0.f));
        ull wr[4];
#pragma unroll
        for (int j = 0; j < 4; j++) wr[j] = s_w[ci][ocg*4 + j];
#pragma unroll
        for (int j = 0; j < 4; j++) {
            ffma2(acc[0][j], b0, wr[j]);
            ffma2(acc[1][j], b1, wr[j]);
            ffma2(acc[2][j], b2, wr[j]);
            ffma2(acc[3][j], b3, wr[j]);
        }
    }
#pragma unroll
    for (int j = 0; j < 4; j++) {
#pragma unroll
        for (int lane = 0; lane < 2; lane++) {
            int oc = ocb + ocg*8 + 2*j + lane;
            size_t base = (((size_t)b*Cout + oc) << 10) + s0;
            float bv = bias ? bias[oc] : 0.f;
            float4 hv = make_float4(0.f, 0.f, 0.f, 0.f);
            if (hres) hv = *(const float4*)&hres[base];
            float4 ov;
            ov.x = (lane ? hi32(acc[0][j]) : lo32(acc[0][j])) + bv + hv.x;
            ov.y = (lane ? hi32(acc[1][j]) : lo32(acc[1][j])) + bv + hv.y;
            ov.z = (lane ? hi32(acc[2][j]) : lo32(acc[2][j])) + bv + hv.z;
            ov.w = (lane ? hi32(acc[3][j]) : lo32(acc[3][j])) + bv + hv.w;
            *(float4*)&out[base] = ov;
        }
    }
}

// ---------------- vector quantizer ----------------
__global__ void vq_kernel(const float* __restrict__ z, const float* __restrict__ cb,
                          float* __restrict__ qc, int* __restrict__ hist,
                          float* __restrict__ ssep)
{
    __shared__ ull s_cb[128][32];
    __shared__ float s_cn[128];
    __shared__ int s_hist[512];
    __shared__ float s_red[128];
    int tid = threadIdx.x;
    for (int i = tid; i < 512; i += 128) s_hist[i] = 0;

    int n = blockIdx.x * 128 + tid;
    int b = n >> 10, s = n & 1023;
    ull zp[32];
    float zv[64];
#pragma unroll
    for (int d = 0; d < 64; d++) zv[d] = z[(((size_t)b * 64 + d) << 10) + s];
#pragma unroll
    for (int j = 0; j < 32; j++) zp[j] = pack2(zv[2*j], zv[2*j+1]);

    const ull* cbu = (const ull*)cb;
    float best = 3.4e38f; int bi = 0;
    for (int k0 = 0; k0 < 512; k0 += 128) {
        __syncthreads();
        for (int i = tid; i < 128*32; i += 128)
            s_cb[i >> 5][i & 31] = cbu[((size_t)k0 << 5) + i];
        __syncthreads();
        {
            float cn = 0.f;
#pragma unroll
            for (int j = 0; j < 32; j++) {
                ull p = s_cb[tid][j];
                float a = lo32(p), bb = hi32(p);
                cn += a*a + bb*bb;
            }
            s_cn[tid] = cn;
        }
        __syncthreads();
        for (int k = 0; k < 128; k++) {
            ull dp = 0ull;
#pragma unroll
            for (int j = 0; j < 32; j++) ffma2(dp, zp[j], s_cb[k][j]);
            float dot = lo32(dp) + hi32(dp);
            float dd = s_cn[k] - 2.f * dot;
            if (dd < best) { best = dd; bi = k0 + k; }
        }
    }
    float sq = 0.f;
    const float* c = cb + ((size_t)bi << 6);
#pragma unroll
    for (int d = 0; d < 64; d++) {
        float cv = c[d];
        qc[(((size_t)b * 64 + d) << 10) + s] = cv;
        float df = cv - zv[d];
        sq += df * df;
    }
    atomicAdd(&s_hist[bi], 1);
    s_red[tid] = sq;
    __syncthreads();
    for (int st = 64; st > 0; st >>= 1) {
        if (tid < st) s_red[tid] += s_red[tid + st];
        __syncthreads();
    }
    if (tid == 0) ssep[blockIdx.x] = s_red[0];
    for (int i = tid; i < 512; i += 128)
        if (s_hist[i]) atomicAdd(&hist[i], s_hist[i]);
}

// ---------------- dt2: convT (64->3), 4-oc scalar ----------------
__global__ void convt4s2_kernel(const float* __restrict__ in, const float* __restrict__ w,
                                const float* __restrict__ bias, float* __restrict__ out,
                                int Cin, int Hin, int Win, int Cout, int inRelu, int outRelu)
{
    __shared__ float s_in[8][10][12];
    __shared__ float s_w[4][8][16];
    int tid = threadIdx.x;
    int Hout = Hin * 2, Wout = Win * 2;
    int ntx = Wout >> 4;
    int ox0 = (blockIdx.x % ntx) << 4, oy0 = (blockIdx.x / ntx) << 4;
    int b = blockIdx.z;
    int px = tid & 15, py = tid >> 4;
    int iy0 = oy0 >> 1, ix0 = ox0 >> 1;
    float acc[4];
#pragma unroll
    for (int i = 0; i < 4; i++) acc[i] = 0.f;

    for (int c0 = 0; c0 < Cin; c0 += 8) {
        for (int i = tid; i < 8 * 10 * 10; i += 256) {
            int ci = i / 100; int rr = (i / 10) % 10; int col = i % 10;
            int gy = iy0 - 1 + rr, gx = ix0 - 1 + col;
            float v = 0.f;
            if ((unsigned)gy < (unsigned)Hin && (unsigned)gx < (unsigned)Win)
                v = in[((b*Cin + c0 + ci)*Hin + gy)*Win + gx];
            if (inRelu) v = fmaxf(v, 0.f);
            s_in[ci][rr][col] = v;
        }
        for (int i = tid; i < 4 * 8 * 16; i += 256) {
            int oc = i >> 7; int ci = (i >> 4) & 7; int k = i & 15;
            s_w[oc][ci][k] = (oc < Cout) ? w[((size_t)oc * Cin + c0 + ci)*16 + k] : 0.f;
        }
        __syncthreads();
        int ky0 = py & 1, kx0 = px & 1;
        int r0 = (py + ky0) >> 1;
        int q0 = (px + kx0) >> 1;
#pragma unroll
        for (int ci = 0; ci < 8; ci++) {
            float v00 = s_in[ci][r0][q0];
            float v01 = s_in[ci][r0][q0 + 1];
            float v10 = s_in[ci][r0 + 1][q0];
            float v11 = s_in[ci][r0 + 1][q0 + 1];
#pragma unroll
            for (int oc = 0; oc < 4; oc++) {
                float a = acc[oc];
                a += v00 * s_w[oc][ci][ky0*4 + kx0];
                a += v01 * s_w[oc][ci][ky0*4 + kx0 + 2];
                a += v10 * s_w[oc][ci][(ky0+2)*4 + kx0];
                a += v11 * s_w[oc][ci][(ky0+2)*4 + kx0 + 2];
                acc[oc] = a;
            }
        }
        __syncthreads();
    }
#pragma unroll
    for (int oc = 0; oc < 4; oc++) {
        if (oc < Cout) {
            float r = acc[oc] + bias[oc];
            if (outRelu) r = fmaxf(r, 0.f);
            out[(((size_t)b * Cout + oc)*Hout + oy0 + py)*Wout + ox0 + px] = r;
        }
    }
}

// ---------------- finalize ----------------
__global__ void finalize_kernel(const int* __restrict__ hist, const float* __restrict__ ssep,
                                float* __restrict__ out, int lastIdx)
{
    __shared__ float red[512];
    __shared__ float red2[256];
    int t = threadIdx.x;
    float p = hist[t] * (1.0f / 32768.0f);
    red[t] = p * logf(p + 1e-10f);
    if (t < 256) red2[t] = ssep[t];
    __syncthreads();
    for (int st = 256; st > 0; st >>= 1) {
        if (t < st) red[t] += red[t + st];
        __syncthreads();
    }
    for (int st = 128; st > 0; st >>= 1) {
        if (t < st) red2[t] += red2[t + st];
        __syncthreads();
    }
    if (t == 0) {
        out[0] = red2[0] * 1.25f / (32768.0f * 64.0f);
        out[lastIdx] = expf(-red[0]);
    }
}

// ---------------- launch ----------------
extern "C" void kernel_launch(void* const* d_in, const int* in_sizes, int n_in,
                              void* d_out, int out_size)
{
    const float* x     = (const float*)d_in[0];
    const float* e_w1  = (const float*)d_in[1];
    const float* e_b1  = (const float*)d_in[2];
    const float* e_w2  = (const float*)d_in[3];
    const float* e_b2  = (const float*)d_in[4];
    const float* e_w3  = (const float*)d_in[5];
    const float* e_b3  = (const float*)d_in[6];
    const float* e_r1a = (const float*)d_in[7];
    const float* e_r1b = (const float*)d_in[8];
    const float* e_r2a = (const float*)d_in[9];
    const float* e_r2b = (const float*)d_in[10];
    const float* pre_w = (const float*)d_in[11];
    const float* pre_b = (const float*)d_in[12];
    const float* cb    = (const float*)d_in[13];
    const float* d_w1  = (const float*)d_in[14];
    const float* d_b1  = (const float*)d_in[15];
    const float* d_r1a = (const float*)d_in[16];
    const float* d_r1b = (const float*)d_in[17];
    const float* d_r2a = (const float*)d_in[18];
    const float* d_r2b = (const float*)d_in[19];
    const float* dt_w1 = (const float*)d_in[20];
    const float* dt_b1 = (const float*)d_in[21];
    const float* dt_w2 = (const float*)d_in[22];
    const float* dt_b2 = (const float*)d_in[23];
    float* out = (float*)d_out;

    float *A, *Bb, *C, *R, *Z, *Q, *ssep; int* hist;
    __nv_bfloat16 *Sh, *Sl, *Gh, *Gl, *Wh, *Wl;
    cudaGetSymbolAddress((void**)&A,    g_A);
    cudaGetSymbolAddress((void**)&Bb,   g_B);
    cudaGetSymbolAddress((void**)&C,    g_C);
    cudaGetSymbolAddress((void**)&R,    g_R);
    cudaGetSymbolAddress((void**)&Z,    g_Z);
    cudaGetSymbolAddress((void**)&Q,    g_Q);
    cudaGetSymbolAddress((void**)&ssep, g_ssep);
    cudaGetSymbolAddress((void**)&hist, g_hist);
    cudaGetSymbolAddress((void**)&Sh,   g_Sh);
    cudaGetSymbolAddress((void**)&Sl,   g_Sl);
    cudaGetSymbolAddress((void**)&Gh,   g_Gh);
    cudaGetSymbolAddress((void**)&Gl,   g_Gl);
    cudaGetSymbolAddress((void**)&Wh,   g_Wh);
    cudaGetSymbolAddress((void**)&Wl,   g_Wl);

    static int smem_set = 0;
    if (!smem_set) {
        cudaFuncSetAttribute(gemm_wmma, cudaFuncAttributeMaxDynamicSharedMemorySize, DYN_SMEM);
        cudaFuncSetAttribute(conv3x3_wmma, cudaFuncAttributeMaxDynamicSharedMemorySize, DYN_SMEM);
        cudaFuncSetAttribute(convt_wmma, cudaFuncAttributeMaxDynamicSharedMemorySize, DYN_SMEM);
        smem_set = 1;
    }

    zero_kernel<<<2, 256>>>(hist);

    // ---- encoder ----
    stage_w_gen<<<16, 256>>>(e_w1, Wh, Wl, 3, 4, 64, 16);
    stage_im2col<<<dim3(64, 8), 256>>>(x, Gh, Gl, 3, 4, 128, 128, 4, 2, 1, 64, 64, BATCH*4096);
    gemm_wmma<<<dim3(1024, 1), 256, DYN_SMEM>>>(Gh, Gl, Wh, Wl, e_b1, A, 64, 64, 64, BATCH*4096, 4096, 1);
    stage_w_gen<<<128, 256>>>(e_w2, Wh, Wl, 64, 64, 128, 16);
    stage_k4s2<<<2048, 256>>>(A, Gh, Gl, BATCH*1024);
    gemm_wmma<<<dim3(256, 2), 256, DYN_SMEM>>>(Gh, Gl, Wh, Wl, e_b2, Bb, 1024, 128, 64, BATCH*1024, 1024, 1);

    stage_w_kernel<<<64, 256>>>(e_w3, Wh, Wl, 128, 128);
    stage_in_kernel<<<4096, 256>>>(Bb, Sh, Sl, 4096, 0);
    conv3x3_wmma<<<dim3(8, 2, BATCH), 256, DYN_SMEM>>>(Sh, Sl, Wh, Wl, e_b3, C, 128, 128, 64, 4096);
    stage_w_kernel<<<64, 256>>>(e_r1a, Wh, Wl, 128, 32);
    stage_in_kernel<<<4096, 256>>>(C, Sh, Sl, 4096, 1);
    conv3x3_wmma<<<dim3(8, 1, BATCH), 256, DYN_SMEM>>>(Sh, Sl, Wh, Wl, nullptr, R, 128, 32, 32, 4096);
    conv1x1_f2_kernel<<<dim3(4, 4, BATCH), 256>>>(R, e_r1b, nullptr, C, C, 32, 128);
    stage_w_kernel<<<64, 256>>>(e_r2a, Wh, Wl, 128, 32);
    stage_in_kernel<<<4096, 256>>>(C, Sh, Sl, 4096, 1);
    conv3x3_wmma<<<dim3(8, 1, BATCH), 256, DYN_SMEM>>>(Sh, Sl, Wh, Wl, nullptr, R, 128, 32, 32, 4096);
    conv1x1_f2_kernel<<<dim3(4, 4, BATCH), 256>>>(R, e_r2b, nullptr, C, C, 32, 128);
    conv1x1_f2_kernel<<<dim3(4, 2, BATCH), 256>>>(C, pre_w, pre_b, nullptr, Z, 128, 64);

    // ---- VQ ----
    vq_kernel<<<256, 128>>>(Z, cb, Q, hist, ssep);

    // ---- decoder ----
    stage_w_kernel<<<64, 256>>>(d_w1, Wh, Wl, 64, 128);
    stage_in_kernel<<<2048, 256>>>(Q, Sh, Sl, 2048, 0);
    conv3x3_wmma<<<dim3(8, 2, BATCH), 256, DYN_SMEM>>>(Sh, Sl, Wh, Wl, d_b1, Bb, 64, 128, 64, 2048);
    stage_w_kernel<<<64, 256>>>(d_r1a, Wh, Wl, 128, 32);
    stage_in_kernel<<<4096, 256>>>(Bb, Sh, Sl, 4096, 1);
    conv3x3_wmma<<<dim3(8, 1, BATCH), 256, DYN_SMEM>>>(Sh, Sl, Wh, Wl, nullptr, R, 128, 32, 32, 4096);
    conv1x1_f2_kernel<<<dim3(4, 4, BATCH), 256>>>(R, d_r1b, nullptr, Bb, Bb, 32, 128);
    stage_w_kernel<<<64, 256>>>(d_r2a, Wh, Wl, 128, 32);
    stage_in_kernel<<<4096, 256>>>(Bb, Sh, Sl, 4096, 1);
    conv3x3_wmma<<<dim3(8, 1, BATCH), 256, DYN_SMEM>>>(Sh, Sl, Wh, Wl, nullptr, R, 128, 32, 32, 4096);
    conv1x1_f2_kernel<<<dim3(4, 4, BATCH), 256>>>(R, d_r2b, nullptr, Bb, Bb, 32, 128);

    // dt1: convT 128->64 via parity GEMMs on tensor cores (reuses shifted-plane staging, relu'd)
    stage_w_dt1<<<128, 256>>>(dt_w1, Wh, Wl);
    stage_in_kernel<<<4096, 256>>>(Bb, Sh, Sl, 4096, 1);
    convt_wmma<<<dim3(8, 4, BATCH), 256, DYN_SMEM>>>(Sh, Sl, Wh, Wl, dt_b1, A, 4096);

    convt4s2_kernel<<<dim3(64, 1, BATCH), 256>>>(A, dt_w2, dt_b2, out + 1, 64, 64, 64, 3, 0, 0);

    finalize_kernel<<<1, 512>>>(hist, ssep, out, out_size - 1);
}